// round 13
// baseline (speedup 1.0000x reference)
#include <cuda_runtime.h>
#include <cuda_bf16.h>
#include <cstdint>

// Problem constants
#define Bsz 128          // batch
#define Tsz 800          // seq len
#define Isz 300          // input dim
#define IszP 304         // padded to 16
#define Hsz 32           // hidden
#define Gsz 128          // 4*H
#define NBH 4096         // B*H
#define NMB 7            // m-blocks in gemm_q (ceil(800/128))

// ---------------- scratch (static __device__, no runtime alloc) -------------
__device__ float g_gx[(size_t)Bsz * Tsz * Gsz];       // [B*T, 4H]  52.4 MB
__device__ float g_hsT[(size_t)Tsz * NBH];            // [T, B*H] fp32
__device__ __nv_bfloat16 g_hsT_hi[(size_t)Tsz * NBH]; // [T, B*H] bf16 hi
__device__ __nv_bfloat16 g_hsT_lo[(size_t)Tsz * NBH]; // [T, B*H] bf16 lo
__device__ __nv_bfloat16 g_Wih_hi[128 * IszP], g_Wih_lo[128 * IszP];
__device__ __nv_bfloat16 g_Ww_hi[800 * 800],  g_Ww_lo[800 * 800];
__device__ float g_fcpart[Bsz * NMB];                 // deterministic partials
__device__ float g_qk_scratch[(size_t)Bsz * Tsz * Hsz];
__device__ float g_fc_scratch[Bsz];

// ---------------- PTX helpers ----------------------------------------------
__device__ __forceinline__ uint32_t sptr(const void* p) {
    return (uint32_t)__cvta_generic_to_shared(p);
}
__device__ __forceinline__ void ldsm4(uint32_t* r, uint32_t a) {
    asm volatile("ldmatrix.sync.aligned.m8n8.x4.shared.b16 {%0,%1,%2,%3}, [%4];"
                 : "=r"(r[0]), "=r"(r[1]), "=r"(r[2]), "=r"(r[3]) : "r"(a));
}
__device__ __forceinline__ void ldsm4t(uint32_t* r, uint32_t a) {
    asm volatile("ldmatrix.sync.aligned.m8n8.x4.trans.shared.b16 {%0,%1,%2,%3}, [%4];"
                 : "=r"(r[0]), "=r"(r[1]), "=r"(r[2]), "=r"(r[3]) : "r"(a));
}
__device__ __forceinline__ void mma16816(float* d, const uint32_t* a, const uint32_t* b) {
    asm volatile(
        "mma.sync.aligned.m16n8k16.row.col.f32.bf16.bf16.f32 "
        "{%0,%1,%2,%3}, {%4,%5,%6,%7}, {%8,%9}, {%0,%1,%2,%3};"
        : "+f"(d[0]), "+f"(d[1]), "+f"(d[2]), "+f"(d[3])
        : "r"(a[0]), "r"(a[1]), "r"(a[2]), "r"(a[3]), "r"(b[0]), "r"(b[1]));
}

// Fast activations: div.approx (single MUFU.RCP) + EX2-based exp.
__device__ __forceinline__ float sigm_(float z) {
    return __fdividef(1.f, 1.f + __expf(-z));
}
__device__ __forceinline__ float tanh_(float z) {
    return fmaf(2.f, __fdividef(1.f, 1.f + __expf(-2.f * z)), -1.f);
}

// Split 8 fp32 -> bf16 hi/lo, one uint4 STS each.
__device__ __forceinline__ void cvt_store8(__nv_bfloat16* dhi, __nv_bfloat16* dlo,
                                           const float* v) {
    uint32_t hi[4], lo[4];
#pragma unroll
    for (int i = 0; i < 4; i++) {
        __nv_bfloat16 h0 = __float2bfloat16(v[2 * i]);
        __nv_bfloat16 h1 = __float2bfloat16(v[2 * i + 1]);
        __nv_bfloat16 l0 = __float2bfloat16(v[2 * i]     - __bfloat162float(h0));
        __nv_bfloat16 l1 = __float2bfloat16(v[2 * i + 1] - __bfloat162float(h1));
        __nv_bfloat162 hh = __halves2bfloat162(h0, h1);
        __nv_bfloat162 ll = __halves2bfloat162(l0, l1);
        hi[i] = *reinterpret_cast<uint32_t*>(&hh);
        lo[i] = *reinterpret_cast<uint32_t*>(&ll);
    }
    *reinterpret_cast<uint4*>(dhi) = make_uint4(hi[0], hi[1], hi[2], hi[3]);
    *reinterpret_cast<uint4*>(dlo) = make_uint4(lo[0], lo[1], lo[2], lo[3]);
}

// ---------------- prep: one-time fp32 -> bf16 hi/lo splits ------------------
__global__ __launch_bounds__(256) void cvt_wih(const float* __restrict__ W) {
    int i = blockIdx.x * 256 + threadIdx.x;
    if (i >= 128 * IszP) return;
    int r = i / IszP, c = i - r * IszP;
    float v = (c < Isz) ? W[r * Isz + c] : 0.f;
    __nv_bfloat16 h = __float2bfloat16(v);
    g_Wih_hi[i] = h;
    g_Wih_lo[i] = __float2bfloat16(v - __bfloat162float(h));
}
__global__ __launch_bounds__(256) void cvt_ww(const float* __restrict__ W) {
    int i = blockIdx.x * 256 + threadIdx.x;
    if (i >= 800 * 800) return;
    float v = W[i];
    __nv_bfloat16 h = __float2bfloat16(v);
    g_Ww_hi[i] = h;
    g_Ww_lo[i] = __float2bfloat16(v - __bfloat162float(h));
}

// ============================================================================
// Kernel 1: gx = x @ W_ih^T + (b_ih + b_hh), split-bf16 HMMA, pipelined.
// ============================================================================
#define APAD 24
#define NIT1 (IszP / 16)     // 19
__global__ __launch_bounds__(256, 2) void gemm_gx_mma(
    const float* __restrict__ X,
    const float* __restrict__ bih, const float* __restrict__ bhh) {
    __shared__ __align__(16) __nv_bfloat16 sAhi[2][128 * APAD], sAlo[2][128 * APAD];
    __shared__ __align__(16) __nv_bfloat16 sBhi[2][128 * APAD], sBlo[2][128 * APAD];

    const int m0   = blockIdx.x * 128;
    const int tid  = threadIdx.x;
    const int lane = tid & 31;
    const int wid  = tid >> 5;
    const int wm   = wid >> 1;
    const int wn   = wid & 1;

    float acc[2][8][4];
#pragma unroll
    for (int mi = 0; mi < 2; mi++)
#pragma unroll
        for (int ni = 0; ni < 8; ni++)
#pragma unroll
            for (int e = 0; e < 4; e++) acc[mi][ni][e] = 0.f;

    const int lr = tid >> 1;
    const int lk = (tid & 1) * 8;

    const int amrow = lane & 15;
    const int akcol = (lane >> 4) * 8;
    int offA[2];
#pragma unroll
    for (int mi = 0; mi < 2; mi++)
        offA[mi] = (wm * 32 + mi * 16 + amrow) * APAD + akcol;
    const int bnrow = (lane & 7) + ((lane & 16) >> 1);
    const int bkcol = (lane & 8) ? 8 : 0;
    int offB[4];
#pragma unroll
    for (int nb = 0; nb < 4; nb++)
        offB[nb] = (wn * 64 + nb * 16 + bnrow) * APAD + bkcol;

    float va[8];
    uint4 pbh, pbl;

    auto loadA = [&](int k0) {
        if (k0 + lk + 7 < Isz) {
            *(float4*)&va[0] = *(const float4*)&X[(size_t)(m0 + lr) * Isz + k0 + lk];
            *(float4*)&va[4] = *(const float4*)&X[(size_t)(m0 + lr) * Isz + k0 + lk + 4];
        } else {
#pragma unroll
            for (int j = 0; j < 8; j++) {
                int k = k0 + lk + j;
                va[j] = (k < Isz) ? X[(size_t)(m0 + lr) * Isz + k] : 0.f;
            }
        }
    };
    auto loadB = [&](int k0) {
        pbh = *(const uint4*)&g_Wih_hi[lr * IszP + k0 + lk];
        pbl = *(const uint4*)&g_Wih_lo[lr * IszP + k0 + lk];
    };
    auto stA = [&](int buf) {
        cvt_store8(&sAhi[buf][lr * APAD + lk], &sAlo[buf][lr * APAD + lk], va);
    };
    auto stB = [&](int buf) {
        *(uint4*)&sBhi[buf][lr * APAD + lk] = pbh;
        *(uint4*)&sBlo[buf][lr * APAD + lk] = pbl;
    };

    loadA(0); loadB(0);
    stA(0); stB(0);
    __syncthreads();

#pragma unroll 1
    for (int it = 0; it < NIT1; it++) {
        const int cur = it & 1;
        const bool more = (it + 1 < NIT1);
        if (more) { loadA((it + 1) * 16); loadB((it + 1) * 16); }

        uint32_t afr[2][4], alo[2][4], bfr[8][2];
        ldsm4(afr[0], sptr(&sAhi[cur][offA[0]]));
        ldsm4(afr[1], sptr(&sAhi[cur][offA[1]]));
#pragma unroll
        for (int nb = 0; nb < 4; nb++) {
            uint32_t r[4];
            ldsm4(r, sptr(&sBhi[cur][offB[nb]]));
            bfr[2 * nb][0] = r[0]; bfr[2 * nb][1] = r[1];
            bfr[2 * nb + 1][0] = r[2]; bfr[2 * nb + 1][1] = r[3];
        }
#pragma unroll
        for (int mi = 0; mi < 2; mi++)
#pragma unroll
            for (int ni = 0; ni < 8; ni++) mma16816(acc[mi][ni], afr[mi], bfr[ni]);

        ldsm4(alo[0], sptr(&sAlo[cur][offA[0]]));
        ldsm4(alo[1], sptr(&sAlo[cur][offA[1]]));
#pragma unroll
        for (int mi = 0; mi < 2; mi++)
#pragma unroll
            for (int ni = 0; ni < 8; ni++) mma16816(acc[mi][ni], alo[mi], bfr[ni]);

#pragma unroll
        for (int nb = 0; nb < 4; nb++) {
            uint32_t r[4];
            ldsm4(r, sptr(&sBlo[cur][offB[nb]]));
            bfr[2 * nb][0] = r[0]; bfr[2 * nb][1] = r[1];
            bfr[2 * nb + 1][0] = r[2]; bfr[2 * nb + 1][1] = r[3];
        }
#pragma unroll
        for (int mi = 0; mi < 2; mi++)
#pragma unroll
            for (int ni = 0; ni < 8; ni++) mma16816(acc[mi][ni], afr[mi], bfr[ni]);

        if (more) { stA(cur ^ 1); stB(cur ^ 1); }
        __syncthreads();
    }

    const int er = lane >> 2;
    const int ec = (lane & 3) * 2;
    float bias0[8], bias1[8];
#pragma unroll
    for (int ni = 0; ni < 8; ni++) {
        int col = wn * 64 + ni * 8 + ec;
        bias0[ni] = bih[col] + bhh[col];
        bias1[ni] = bih[col + 1] + bhh[col + 1];
    }
#pragma unroll
    for (int mi = 0; mi < 2; mi++) {
        int row = m0 + wm * 32 + mi * 16 + er;
#pragma unroll
        for (int ni = 0; ni < 8; ni++) {
            int col = wn * 64 + ni * 8 + ec;
            float2 v0 = make_float2(acc[mi][ni][0] + bias0[ni], acc[mi][ni][1] + bias1[ni]);
            float2 v1 = make_float2(acc[mi][ni][2] + bias0[ni], acc[mi][ni][3] + bias1[ni]);
            *(float2*)&g_gx[(size_t)row * Gsz + col]       = v0;
            *(float2*)&g_gx[(size_t)(row + 8) * Gsz + col] = v1;
        }
    }
}

// ============================================================================
// Kernel 2: LSTM recurrence — 128 threads / batch element, NO shfl chains.
// Thread j = gate row (gate=wid, unit=lane). Each warp keeps a PRIVATE smem
// copy of h[0..31] (written by its own lanes, read next step via 8 broadcast
// LDS.128 — intra-warp only, ordered by __syncwarp). Activations exchanged
// gate-major (conflict-free STS.32 / LDS.32) through a double-buffered tile
// with ONE __syncthreads per step. gx ring-prefetched 4 steps deep (DRAM
// latency @NAT ~1000cyc < 3.5-step slack).
// ============================================================================
__global__ __launch_bounds__(128) void lstm_scan(const float* __restrict__ Whh) {
    const int b    = blockIdx.x;
    const int j    = threadIdx.x;
    const int lane = j & 31;
    const int wid  = j >> 5;
    __shared__ float sh_act[2][Gsz];                  // [buf][gate*32 + unit]
    __shared__ __align__(16) float sh_h[4][Hsz];      // per-warp private h

    float w[Hsz];
#pragma unroll
    for (int k = 0; k < Hsz; k++) w[k] = Whh[j * Hsz + k];

    float c = 0.f, h = 0.f;
    sh_h[wid][lane] = 0.f;
    __syncwarp();

    const float* gxb = g_gx + (size_t)b * Tsz * Gsz;
    float gq[4];
#pragma unroll
    for (int p = 0; p < 4; p++) gq[p] = gxb[(size_t)p * Gsz + j];

    const bool is_g = (wid == 2);

    for (int t = 0; t < Tsz; t++) {
        const int sl = t & 3;
        float gcur = gq[sl];
        if (t + 4 < Tsz) gq[sl] = gxb[(size_t)(t + 4) * Gsz + j];  // 4-deep ring

        // hv from this warp's private copy: 8 broadcast LDS.128
        float hv[Hsz];
#pragma unroll
        for (int q = 0; q < Hsz / 4; q++)
            *(float4*)&hv[q * 4] = *(const float4*)&sh_h[wid][q * 4];

        // z = gx + W_hh[j,:] . h   (4-way split chains)
        float s0 = gcur, s1 = 0.f, s2 = 0.f, s3 = 0.f;
#pragma unroll
        for (int k = 0; k < Hsz; k += 4) {
            s0 = fmaf(w[k],     hv[k],     s0);
            s1 = fmaf(w[k + 1], hv[k + 1], s1);
            s2 = fmaf(w[k + 2], hv[k + 2], s2);
            s3 = fmaf(w[k + 3], hv[k + 3], s3);
        }
        float z = (s0 + s1) + (s2 + s3);

        float a = is_g ? tanh_(z) : sigm_(z);
        sh_act[t & 1][wid * Hsz + lane] = a;          // conflict-free STS.32
        __syncthreads();

        // gather (i,f,g,o) for unit=lane: 4 conflict-free LDS.32
        float ig = sh_act[t & 1][lane];
        float fg = sh_act[t & 1][Hsz + lane];
        float gg = sh_act[t & 1][2 * Hsz + lane];
        float og = sh_act[t & 1][3 * Hsz + lane];
        c = fmaf(fg, c, ig * gg);
        h = og * tanh_(c);

        if (wid == 0) {
            size_t idx = (size_t)t * NBH + b * Hsz + lane;
            g_hsT[idx] = h;
            __nv_bfloat16 hh = __float2bfloat16(h);
            g_hsT_hi[idx] = hh;
            g_hsT_lo[idx] = __float2bfloat16(h - __bfloat162float(hh));
        }

        sh_h[wid][lane] = h;                          // own region, no bar
        __syncwarp();
    }
}

// ============================================================================
// Kernel 3: attention GEMM + fused qk/fc epilogue (unchanged)
// ============================================================================
#define BPAD 136
#define NIT2 (Tsz / 16)      // 50
__global__ __launch_bounds__(256, 2) void gemm_q_mma(
    const float* __restrict__ bw, const float* __restrict__ Wfc,
    float* __restrict__ qk_out) {
    __shared__ __align__(16) __nv_bfloat16 sAhi[2][128 * APAD], sAlo[2][128 * APAD];
    __shared__ __align__(16) __nv_bfloat16 sBhi[2][16 * BPAD],  sBlo[2][16 * BPAD];
    __shared__ float redfc[512];

    const int m0   = blockIdx.x * 128;
    const int n0   = blockIdx.y * 128;
    const int tid  = threadIdx.x;
    const int lane = tid & 31;
    const int wid  = tid >> 5;
    const int wm   = wid >> 1;
    const int wn   = wid & 1;

    float acc[2][8][4];
#pragma unroll
    for (int mi = 0; mi < 2; mi++)
#pragma unroll
        for (int ni = 0; ni < 8; ni++)
#pragma unroll
            for (int e = 0; e < 4; e++) acc[mi][ni][e] = 0.f;

    const int alr = tid >> 1;
    const int alk = (tid & 1) * 8;
    const int blr = tid >> 4;
    const int bln = (tid & 15) * 8;
    const bool arow_ok = (m0 + alr < Tsz);

    const int amrow = lane & 15;
    const int akcol = (lane >> 4) * 8;
    int offA[2];
#pragma unroll
    for (int mi = 0; mi < 2; mi++)
        offA[mi] = (wm * 32 + mi * 16 + amrow) * APAD + akcol;
    const int qbrow = lane & 15;
    const int qbcol = (lane >> 4) * 8;
    int offB[4];
#pragma unroll
    for (int nb = 0; nb < 4; nb++)
        offB[nb] = qbrow * BPAD + wn * 64 + nb * 16 + qbcol;

    uint4 pah, pal, pbh, pbl;
    auto loadA = [&](int k0) {
        if (arow_ok) {
            pah = *(const uint4*)&g_Ww_hi[(size_t)(m0 + alr) * Tsz + k0 + alk];
            pal = *(const uint4*)&g_Ww_lo[(size_t)(m0 + alr) * Tsz + k0 + alk];
        } else {
            pah = make_uint4(0, 0, 0, 0);
            pal = make_uint4(0, 0, 0, 0);
        }
    };
    auto loadB = [&](int k0) {
        pbh = *(const uint4*)&g_hsT_hi[(size_t)(k0 + blr) * NBH + n0 + bln];
        pbl = *(const uint4*)&g_hsT_lo[(size_t)(k0 + blr) * NBH + n0 + bln];
    };
    auto stA = [&](int buf) {
        *(uint4*)&sAhi[buf][alr * APAD + alk] = pah;
        *(uint4*)&sAlo[buf][alr * APAD + alk] = pal;
    };
    auto stB = [&](int buf) {
        *(uint4*)&sBhi[buf][blr * BPAD + bln] = pbh;
        *(uint4*)&sBlo[buf][blr * BPAD + bln] = pbl;
    };

    loadA(0); loadB(0);
    stA(0); stB(0);
    __syncthreads();

#pragma unroll 1
    for (int it = 0; it < NIT2; it++) {
        const int cur = it & 1;
        const bool more = (it + 1 < NIT2);
        if (more) { loadA((it + 1) * 16); loadB((it + 1) * 16); }

        uint32_t afr[2][4], alo2[2][4], bfr[8][2];
        ldsm4(afr[0], sptr(&sAhi[cur][offA[0]]));
        ldsm4(afr[1], sptr(&sAhi[cur][offA[1]]));
#pragma unroll
        for (int nb = 0; nb < 4; nb++) {
            uint32_t r[4];
            ldsm4t(r, sptr(&sBhi[cur][offB[nb]]));
            bfr[2 * nb][0] = r[0]; bfr[2 * nb][1] = r[1];
            bfr[2 * nb + 1][0] = r[2]; bfr[2 * nb + 1][1] = r[3];
        }
#pragma unroll
        for (int mi = 0; mi < 2; mi++)
#pragma unroll
            for (int ni = 0; ni < 8; ni++) mma16816(acc[mi][ni], afr[mi], bfr[ni]);

        ldsm4(alo2[0], sptr(&sAlo[cur][offA[0]]));
        ldsm4(alo2[1], sptr(&sAlo[cur][offA[1]]));
#pragma unroll
        for (int mi = 0; mi < 2; mi++)
#pragma unroll
            for (int ni = 0; ni < 8; ni++) mma16816(acc[mi][ni], alo2[mi], bfr[ni]);

#pragma unroll
        for (int nb = 0; nb < 4; nb++) {
            uint32_t r[4];
            ldsm4t(r, sptr(&sBlo[cur][offB[nb]]));
            bfr[2 * nb][0] = r[0]; bfr[2 * nb][1] = r[1];
            bfr[2 * nb + 1][0] = r[2]; bfr[2 * nb + 1][1] = r[3];
        }
#pragma unroll
        for (int mi = 0; mi < 2; mi++)
#pragma unroll
            for (int ni = 0; ni < 8; ni++) mma16816(acc[mi][ni], afr[mi], bfr[ni]);

        if (more) { stA(cur ^ 1); stB(cur ^ 1); }
        __syncthreads();
    }

    // ---- fused epilogue: qk = hsT*(q+bw), fc partials ----
    const int er = lane >> 2;
    const int ec = (lane & 3) * 2;
    float pb[2] = {0.f, 0.f};
#pragma unroll
    for (int mi = 0; mi < 2; mi++) {
        int r0 = m0 + wm * 32 + mi * 16 + er;
        int r1 = r0 + 8;
        float bw0 = (r0 < Tsz) ? bw[r0] : 0.f;
        float bw1 = (r1 < Tsz) ? bw[r1] : 0.f;
#pragma unroll
        for (int ni = 0; ni < 8; ni++) {
            int n  = n0 + wn * 64 + ni * 8 + ec;
            int bb = n >> 5, hh = n & 31;
            int bi = ni >> 2;
            if (r0 < Tsz) {
                float2 o = *(const float2*)&g_hsT[(size_t)r0 * NBH + n];
                float2 wf = *(const float2*)&Wfc[r0 * Hsz + hh];
                float2 v = make_float2(o.x * (acc[mi][ni][0] + bw0),
                                       o.y * (acc[mi][ni][1] + bw0));
                *(float2*)&qk_out[(size_t)bb * (Tsz * Hsz) + r0 * Hsz + hh] = v;
                pb[bi] = fmaf(v.x, wf.x, fmaf(v.y, wf.y, pb[bi]));
            }
            if (r1 < Tsz) {
                float2 o = *(const float2*)&g_hsT[(size_t)r1 * NBH + n];
                float2 wf = *(const float2*)&Wfc[r1 * Hsz + hh];
                float2 v = make_float2(o.x * (acc[mi][ni][2] + bw1),
                                       o.y * (acc[mi][ni][3] + bw1));
                *(float2*)&qk_out[(size_t)bb * (Tsz * Hsz) + r1 * Hsz + hh] = v;
                pb[bi] = fmaf(v.x, wf.x, fmaf(v.y, wf.y, pb[bi]));
            }
        }
    }
    redfc[(wn * 2 + 0) * 128 + wm * 32 + lane] = pb[0];
    redfc[(wn * 2 + 1) * 128 + wm * 32 + lane] = pb[1];
    __syncthreads();
    if (wid < 4) {
        float s = redfc[wid * 128 + lane] + redfc[wid * 128 + lane + 32]
                + redfc[wid * 128 + lane + 64] + redfc[wid * 128 + lane + 96];
#pragma unroll
        for (int o = 16; o > 0; o >>= 1) s += __shfl_xor_sync(0xffffffffu, s, o);
        if (lane == 0) g_fcpart[((n0 >> 5) + wid) * NMB + blockIdx.x] = s;
    }
}

// Final fc: out[b] = bfc + sum over 7 m-block partials
__global__ void fc_final(const float* __restrict__ bfc, float* __restrict__ fc_out) {
    int b = threadIdx.x;
    float s = bfc[0];
#pragma unroll
    for (int i = 0; i < NMB; i++) s += g_fcpart[b * NMB + i];
    fc_out[b] = s;
}

// ============================================================================
// Launcher
// ============================================================================
extern "C" void kernel_launch(void* const* d_in, const int* in_sizes, int n_in,
                              void* d_out, int out_size) {
    const float* x   = (const float*)d_in[0];
    const float* Wih = (const float*)d_in[1];
    const float* Whh = (const float*)d_in[2];
    const float* bih = (const float*)d_in[3];
    const float* bhh = (const float*)d_in[4];
    const float* Ww  = (const float*)d_in[5];
    const float* bw  = (const float*)d_in[6];
    const float* Wfc = (const float*)d_in[7];
    const float* bfc = (const float*)d_in[8];
    float* out = (float*)d_out;

    const long QK = (long)Bsz * Tsz * Hsz;
    float* fc_out;
    float* qk_out;
    if (out_size == (int)(QK + Bsz)) {
        fc_out = out;
        qk_out = out + Bsz;
    } else if (out_size == (int)QK) {
        qk_out = out;
        cudaGetSymbolAddress((void**)&fc_out, g_fc_scratch);
    } else {
        fc_out = out;
        cudaGetSymbolAddress((void**)&qk_out, g_qk_scratch);
    }

    // 0. one-time operand splits
    cvt_wih<<<(128 * IszP + 255) / 256, 256>>>(Wih);
    cvt_ww<<<(800 * 800 + 255) / 256, 256>>>(Ww);

    // 1. input projection GEMM (pipelined split-bf16)
    gemm_gx_mma<<<(Bsz * Tsz) / 128, 256>>>(x, bih, bhh);

    // 2. sequential LSTM scan — 128 threads / batch, LDS-based h exchange
    lstm_scan<<<Bsz, 128>>>(Whh);

    // 3. attention GEMM + fused qk/fc epilogue
    dim3 g2(NMB, NBH / 128);                 // (7, 32)
    gemm_q_mma<<<g2, 256>>>(bw, Wfc, qk_out);

    // 4. final fc reduction
    fc_final<<<1, Bsz>>>(bfc, fc_out);
}

// round 14
// speedup vs baseline: 1.5511x; 1.5511x over previous
#include <cuda_runtime.h>
#include <cuda_bf16.h>
#include <cstdint>

// Problem constants
#define Bsz 128          // batch
#define Tsz 800          // seq len
#define Isz 300          // input dim
#define IszP 304         // padded to 16
#define Hsz 32           // hidden
#define Gsz 128          // 4*H
#define NBH 4096         // B*H
#define NMB 7            // m-blocks in gemm_q (ceil(800/128))

// ---------------- scratch (static __device__, no runtime alloc) -------------
__device__ float g_gx[(size_t)Bsz * Tsz * Gsz];       // [B*T, 4H]  52.4 MB
__device__ float g_hsT[(size_t)Tsz * NBH];            // [T, B*H] fp32
__device__ __nv_bfloat16 g_hsT_hi[(size_t)Tsz * NBH]; // [T, B*H] bf16 hi
__device__ __nv_bfloat16 g_hsT_lo[(size_t)Tsz * NBH]; // [T, B*H] bf16 lo
__device__ __nv_bfloat16 g_Wih_hi[128 * IszP], g_Wih_lo[128 * IszP];
__device__ __nv_bfloat16 g_Ww_hi[800 * 800],  g_Ww_lo[800 * 800];
__device__ float g_fcpart[Bsz * NMB];                 // deterministic partials
__device__ float g_qk_scratch[(size_t)Bsz * Tsz * Hsz];
__device__ float g_fc_scratch[Bsz];

// ---------------- PTX helpers ----------------------------------------------
__device__ __forceinline__ uint32_t sptr(const void* p) {
    return (uint32_t)__cvta_generic_to_shared(p);
}
__device__ __forceinline__ void ldsm4(uint32_t* r, uint32_t a) {
    asm volatile("ldmatrix.sync.aligned.m8n8.x4.shared.b16 {%0,%1,%2,%3}, [%4];"
                 : "=r"(r[0]), "=r"(r[1]), "=r"(r[2]), "=r"(r[3]) : "r"(a));
}
__device__ __forceinline__ void ldsm4t(uint32_t* r, uint32_t a) {
    asm volatile("ldmatrix.sync.aligned.m8n8.x4.trans.shared.b16 {%0,%1,%2,%3}, [%4];"
                 : "=r"(r[0]), "=r"(r[1]), "=r"(r[2]), "=r"(r[3]) : "r"(a));
}
__device__ __forceinline__ void mma16816(float* d, const uint32_t* a, const uint32_t* b) {
    asm volatile(
        "mma.sync.aligned.m16n8k16.row.col.f32.bf16.bf16.f32 "
        "{%0,%1,%2,%3}, {%4,%5,%6,%7}, {%8,%9}, {%0,%1,%2,%3};"
        : "+f"(d[0]), "+f"(d[1]), "+f"(d[2]), "+f"(d[3])
        : "r"(a[0]), "r"(a[1]), "r"(a[2]), "r"(a[3]), "r"(b[0]), "r"(b[1]));
}

// Fast activations: div.approx (single MUFU.RCP) + EX2-based exp.
__device__ __forceinline__ float sigm_(float z) {
    return __fdividef(1.f, 1.f + __expf(-z));
}
__device__ __forceinline__ float tanh_(float z) {
    return fmaf(2.f, __fdividef(1.f, 1.f + __expf(-2.f * z)), -1.f);
}

// Split 8 fp32 -> bf16 hi/lo, one uint4 STS each.
__device__ __forceinline__ void cvt_store8(__nv_bfloat16* dhi, __nv_bfloat16* dlo,
                                           const float* v) {
    uint32_t hi[4], lo[4];
#pragma unroll
    for (int i = 0; i < 4; i++) {
        __nv_bfloat16 h0 = __float2bfloat16(v[2 * i]);
        __nv_bfloat16 h1 = __float2bfloat16(v[2 * i + 1]);
        __nv_bfloat16 l0 = __float2bfloat16(v[2 * i]     - __bfloat162float(h0));
        __nv_bfloat16 l1 = __float2bfloat16(v[2 * i + 1] - __bfloat162float(h1));
        __nv_bfloat162 hh = __halves2bfloat162(h0, h1);
        __nv_bfloat162 ll = __halves2bfloat162(l0, l1);
        hi[i] = *reinterpret_cast<uint32_t*>(&hh);
        lo[i] = *reinterpret_cast<uint32_t*>(&ll);
    }
    *reinterpret_cast<uint4*>(dhi) = make_uint4(hi[0], hi[1], hi[2], hi[3]);
    *reinterpret_cast<uint4*>(dlo) = make_uint4(lo[0], lo[1], lo[2], lo[3]);
}

// ---------------- prep: one-time fp32 -> bf16 hi/lo splits ------------------
__global__ __launch_bounds__(256) void cvt_wih(const float* __restrict__ W) {
    int i = blockIdx.x * 256 + threadIdx.x;
    if (i >= 128 * IszP) return;
    int r = i / IszP, c = i - r * IszP;
    float v = (c < Isz) ? W[r * Isz + c] : 0.f;
    __nv_bfloat16 h = __float2bfloat16(v);
    g_Wih_hi[i] = h;
    g_Wih_lo[i] = __float2bfloat16(v - __bfloat162float(h));
}
__global__ __launch_bounds__(256) void cvt_ww(const float* __restrict__ W) {
    int i = blockIdx.x * 256 + threadIdx.x;
    if (i >= 800 * 800) return;
    float v = W[i];
    __nv_bfloat16 h = __float2bfloat16(v);
    g_Ww_hi[i] = h;
    g_Ww_lo[i] = __float2bfloat16(v - __bfloat162float(h));
}

// ============================================================================
// Kernel 1: gx = x @ W_ih^T + (b_ih + b_hh), split-bf16 HMMA, pipelined.
// ============================================================================
#define APAD 24
#define NIT1 (IszP / 16)     // 19
__global__ __launch_bounds__(256, 2) void gemm_gx_mma(
    const float* __restrict__ X,
    const float* __restrict__ bih, const float* __restrict__ bhh) {
    __shared__ __align__(16) __nv_bfloat16 sAhi[2][128 * APAD], sAlo[2][128 * APAD];
    __shared__ __align__(16) __nv_bfloat16 sBhi[2][128 * APAD], sBlo[2][128 * APAD];

    const int m0   = blockIdx.x * 128;
    const int tid  = threadIdx.x;
    const int lane = tid & 31;
    const int wid  = tid >> 5;
    const int wm   = wid >> 1;
    const int wn   = wid & 1;

    float acc[2][8][4];
#pragma unroll
    for (int mi = 0; mi < 2; mi++)
#pragma unroll
        for (int ni = 0; ni < 8; ni++)
#pragma unroll
            for (int e = 0; e < 4; e++) acc[mi][ni][e] = 0.f;

    const int lr = tid >> 1;
    const int lk = (tid & 1) * 8;

    const int amrow = lane & 15;
    const int akcol = (lane >> 4) * 8;
    int offA[2];
#pragma unroll
    for (int mi = 0; mi < 2; mi++)
        offA[mi] = (wm * 32 + mi * 16 + amrow) * APAD + akcol;
    const int bnrow = (lane & 7) + ((lane & 16) >> 1);
    const int bkcol = (lane & 8) ? 8 : 0;
    int offB[4];
#pragma unroll
    for (int nb = 0; nb < 4; nb++)
        offB[nb] = (wn * 64 + nb * 16 + bnrow) * APAD + bkcol;

    float va[8];
    uint4 pbh, pbl;

    auto loadA = [&](int k0) {
        if (k0 + lk + 7 < Isz) {
            *(float4*)&va[0] = *(const float4*)&X[(size_t)(m0 + lr) * Isz + k0 + lk];
            *(float4*)&va[4] = *(const float4*)&X[(size_t)(m0 + lr) * Isz + k0 + lk + 4];
        } else {
#pragma unroll
            for (int j = 0; j < 8; j++) {
                int k = k0 + lk + j;
                va[j] = (k < Isz) ? X[(size_t)(m0 + lr) * Isz + k] : 0.f;
            }
        }
    };
    auto loadB = [&](int k0) {
        pbh = *(const uint4*)&g_Wih_hi[lr * IszP + k0 + lk];
        pbl = *(const uint4*)&g_Wih_lo[lr * IszP + k0 + lk];
    };
    auto stA = [&](int buf) {
        cvt_store8(&sAhi[buf][lr * APAD + lk], &sAlo[buf][lr * APAD + lk], va);
    };
    auto stB = [&](int buf) {
        *(uint4*)&sBhi[buf][lr * APAD + lk] = pbh;
        *(uint4*)&sBlo[buf][lr * APAD + lk] = pbl;
    };

    loadA(0); loadB(0);
    stA(0); stB(0);
    __syncthreads();

#pragma unroll 1
    for (int it = 0; it < NIT1; it++) {
        const int cur = it & 1;
        const bool more = (it + 1 < NIT1);
        if (more) { loadA((it + 1) * 16); loadB((it + 1) * 16); }

        uint32_t afr[2][4], alo[2][4], bfr[8][2];
        ldsm4(afr[0], sptr(&sAhi[cur][offA[0]]));
        ldsm4(afr[1], sptr(&sAhi[cur][offA[1]]));
#pragma unroll
        for (int nb = 0; nb < 4; nb++) {
            uint32_t r[4];
            ldsm4(r, sptr(&sBhi[cur][offB[nb]]));
            bfr[2 * nb][0] = r[0]; bfr[2 * nb][1] = r[1];
            bfr[2 * nb + 1][0] = r[2]; bfr[2 * nb + 1][1] = r[3];
        }
#pragma unroll
        for (int mi = 0; mi < 2; mi++)
#pragma unroll
            for (int ni = 0; ni < 8; ni++) mma16816(acc[mi][ni], afr[mi], bfr[ni]);

        ldsm4(alo[0], sptr(&sAlo[cur][offA[0]]));
        ldsm4(alo[1], sptr(&sAlo[cur][offA[1]]));
#pragma unroll
        for (int mi = 0; mi < 2; mi++)
#pragma unroll
            for (int ni = 0; ni < 8; ni++) mma16816(acc[mi][ni], alo[mi], bfr[ni]);

#pragma unroll
        for (int nb = 0; nb < 4; nb++) {
            uint32_t r[4];
            ldsm4(r, sptr(&sBlo[cur][offB[nb]]));
            bfr[2 * nb][0] = r[0]; bfr[2 * nb][1] = r[1];
            bfr[2 * nb + 1][0] = r[2]; bfr[2 * nb + 1][1] = r[3];
        }
#pragma unroll
        for (int mi = 0; mi < 2; mi++)
#pragma unroll
            for (int ni = 0; ni < 8; ni++) mma16816(acc[mi][ni], afr[mi], bfr[ni]);

        if (more) { stA(cur ^ 1); stB(cur ^ 1); }
        __syncthreads();
    }

    const int er = lane >> 2;
    const int ec = (lane & 3) * 2;
    float bias0[8], bias1[8];
#pragma unroll
    for (int ni = 0; ni < 8; ni++) {
        int col = wn * 64 + ni * 8 + ec;
        bias0[ni] = bih[col] + bhh[col];
        bias1[ni] = bih[col + 1] + bhh[col + 1];
    }
#pragma unroll
    for (int mi = 0; mi < 2; mi++) {
        int row = m0 + wm * 32 + mi * 16 + er;
#pragma unroll
        for (int ni = 0; ni < 8; ni++) {
            int col = wn * 64 + ni * 8 + ec;
            float2 v0 = make_float2(acc[mi][ni][0] + bias0[ni], acc[mi][ni][1] + bias1[ni]);
            float2 v1 = make_float2(acc[mi][ni][2] + bias0[ni], acc[mi][ni][3] + bias1[ni]);
            *(float2*)&g_gx[(size_t)row * Gsz + col]       = v0;
            *(float2*)&g_gx[(size_t)(row + 8) * Gsz + col] = v1;
        }
    }
}

// ============================================================================
// Kernel 2: LSTM recurrence — R12 structure (best measured: 128 thr, shfl-h,
// one bar/step, fast activations) + distance-8 gx prefetch ring with ALL
// STATIC indexing (outer tt loop, fully-unrolled k in [0,8): gq[k] is a
// compile-time register, never local memory).
// ============================================================================
__global__ __launch_bounds__(128) void lstm_scan(const float* __restrict__ Whh) {
    const int b    = blockIdx.x;
    const int j    = threadIdx.x;
    const int lane = j & 31;
    const int wid  = j >> 5;
    __shared__ __align__(16) float sh_act[2][Gsz];   // [buf][unit*4 + gate]

    float w[Hsz];
#pragma unroll
    for (int k = 0; k < Hsz; k++) w[k] = Whh[j * Hsz + k];

    float c = 0.f, h = 0.f;
    const float* gxb = g_gx + (size_t)b * Tsz * Gsz;

    // distance-8 prefetch ring (static registers)
    float gq[8];
#pragma unroll
    for (int k = 0; k < 8; k++) gq[k] = gxb[(size_t)k * Gsz + j];

    const bool is_g = (wid == 2);

#pragma unroll 1
    for (int tt = 0; tt < Tsz; tt += 8) {
#pragma unroll
        for (int k = 0; k < 8; k++) {
            const int t = tt + k;
            float gcur = gq[k];
            if (t + 8 < Tsz) gq[k] = gxb[(size_t)(t + 8) * Gsz + j];

            // z = gx + W_hh[j,:] . h  (h broadcast via shfl, 4-way split)
            float s0 = gcur, s1 = 0.f, s2 = 0.f, s3 = 0.f;
#pragma unroll
            for (int q = 0; q < Hsz; q += 4) {
                s0 = fmaf(w[q],     __shfl_sync(0xffffffffu, h, q),     s0);
                s1 = fmaf(w[q + 1], __shfl_sync(0xffffffffu, h, q + 1), s1);
                s2 = fmaf(w[q + 2], __shfl_sync(0xffffffffu, h, q + 2), s2);
                s3 = fmaf(w[q + 3], __shfl_sync(0xffffffffu, h, q + 3), s3);
            }
            float z = (s0 + s1) + (s2 + s3);

            float a = is_g ? tanh_(z) : sigm_(z);
            sh_act[k & 1][lane * 4 + wid] = a;
            __syncthreads();

            float4 g4 = *(const float4*)&sh_act[k & 1][lane * 4];  // (i,f,g,o)
            c = fmaf(g4.y, c, g4.x * g4.z);
            h = g4.w * tanh_(c);
            if (wid == 0) {
                size_t idx = (size_t)t * NBH + b * Hsz + lane;
                g_hsT[idx] = h;
                __nv_bfloat16 hh = __float2bfloat16(h);
                g_hsT_hi[idx] = hh;
                g_hsT_lo[idx] = __float2bfloat16(h - __bfloat162float(hh));
            }
        }
    }
}

// ============================================================================
// Kernel 3: attention GEMM + fused qk/fc epilogue (unchanged)
// ============================================================================
#define BPAD 136
#define NIT2 (Tsz / 16)      // 50
__global__ __launch_bounds__(256, 2) void gemm_q_mma(
    const float* __restrict__ bw, const float* __restrict__ Wfc,
    float* __restrict__ qk_out) {
    __shared__ __align__(16) __nv_bfloat16 sAhi[2][128 * APAD], sAlo[2][128 * APAD];
    __shared__ __align__(16) __nv_bfloat16 sBhi[2][16 * BPAD],  sBlo[2][16 * BPAD];
    __shared__ float redfc[512];

    const int m0   = blockIdx.x * 128;
    const int n0   = blockIdx.y * 128;
    const int tid  = threadIdx.x;
    const int lane = tid & 31;
    const int wid  = tid >> 5;
    const int wm   = wid >> 1;
    const int wn   = wid & 1;

    float acc[2][8][4];
#pragma unroll
    for (int mi = 0; mi < 2; mi++)
#pragma unroll
        for (int ni = 0; ni < 8; ni++)
#pragma unroll
            for (int e = 0; e < 4; e++) acc[mi][ni][e] = 0.f;

    const int alr = tid >> 1;
    const int alk = (tid & 1) * 8;
    const int blr = tid >> 4;
    const int bln = (tid & 15) * 8;
    const bool arow_ok = (m0 + alr < Tsz);

    const int amrow = lane & 15;
    const int akcol = (lane >> 4) * 8;
    int offA[2];
#pragma unroll
    for (int mi = 0; mi < 2; mi++)
        offA[mi] = (wm * 32 + mi * 16 + amrow) * APAD + akcol;
    const int qbrow = lane & 15;
    const int qbcol = (lane >> 4) * 8;
    int offB[4];
#pragma unroll
    for (int nb = 0; nb < 4; nb++)
        offB[nb] = qbrow * BPAD + wn * 64 + nb * 16 + qbcol;

    uint4 pah, pal, pbh, pbl;
    auto loadA = [&](int k0) {
        if (arow_ok) {
            pah = *(const uint4*)&g_Ww_hi[(size_t)(m0 + alr) * Tsz + k0 + alk];
            pal = *(const uint4*)&g_Ww_lo[(size_t)(m0 + alr) * Tsz + k0 + alk];
        } else {
            pah = make_uint4(0, 0, 0, 0);
            pal = make_uint4(0, 0, 0, 0);
        }
    };
    auto loadB = [&](int k0) {
        pbh = *(const uint4*)&g_hsT_hi[(size_t)(k0 + blr) * NBH + n0 + bln];
        pbl = *(const uint4*)&g_hsT_lo[(size_t)(k0 + blr) * NBH + n0 + bln];
    };
    auto stA = [&](int buf) {
        *(uint4*)&sAhi[buf][alr * APAD + alk] = pah;
        *(uint4*)&sAlo[buf][alr * APAD + alk] = pal;
    };
    auto stB = [&](int buf) {
        *(uint4*)&sBhi[buf][blr * BPAD + bln] = pbh;
        *(uint4*)&sBlo[buf][blr * BPAD + bln] = pbl;
    };

    loadA(0); loadB(0);
    stA(0); stB(0);
    __syncthreads();

#pragma unroll 1
    for (int it = 0; it < NIT2; it++) {
        const int cur = it & 1;
        const bool more = (it + 1 < NIT2);
        if (more) { loadA((it + 1) * 16); loadB((it + 1) * 16); }

        uint32_t afr[2][4], alo2[2][4], bfr[8][2];
        ldsm4(afr[0], sptr(&sAhi[cur][offA[0]]));
        ldsm4(afr[1], sptr(&sAhi[cur][offA[1]]));
#pragma unroll
        for (int nb = 0; nb < 4; nb++) {
            uint32_t r[4];
            ldsm4t(r, sptr(&sBhi[cur][offB[nb]]));
            bfr[2 * nb][0] = r[0]; bfr[2 * nb][1] = r[1];
            bfr[2 * nb + 1][0] = r[2]; bfr[2 * nb + 1][1] = r[3];
        }
#pragma unroll
        for (int mi = 0; mi < 2; mi++)
#pragma unroll
            for (int ni = 0; ni < 8; ni++) mma16816(acc[mi][ni], afr[mi], bfr[ni]);

        ldsm4(alo2[0], sptr(&sAlo[cur][offA[0]]));
        ldsm4(alo2[1], sptr(&sAlo[cur][offA[1]]));
#pragma unroll
        for (int mi = 0; mi < 2; mi++)
#pragma unroll
            for (int ni = 0; ni < 8; ni++) mma16816(acc[mi][ni], alo2[mi], bfr[ni]);

#pragma unroll
        for (int nb = 0; nb < 4; nb++) {
            uint32_t r[4];
            ldsm4t(r, sptr(&sBlo[cur][offB[nb]]));
            bfr[2 * nb][0] = r[0]; bfr[2 * nb][1] = r[1];
            bfr[2 * nb + 1][0] = r[2]; bfr[2 * nb + 1][1] = r[3];
        }
#pragma unroll
        for (int mi = 0; mi < 2; mi++)
#pragma unroll
            for (int ni = 0; ni < 8; ni++) mma16816(acc[mi][ni], afr[mi], bfr[ni]);

        if (more) { stA(cur ^ 1); stB(cur ^ 1); }
        __syncthreads();
    }

    // ---- fused epilogue: qk = hsT*(q+bw), fc partials ----
    const int er = lane >> 2;
    const int ec = (lane & 3) * 2;
    float pb[2] = {0.f, 0.f};
#pragma unroll
    for (int mi = 0; mi < 2; mi++) {
        int r0 = m0 + wm * 32 + mi * 16 + er;
        int r1 = r0 + 8;
        float bw0 = (r0 < Tsz) ? bw[r0] : 0.f;
        float bw1 = (r1 < Tsz) ? bw[r1] : 0.f;
#pragma unroll
        for (int ni = 0; ni < 8; ni++) {
            int n  = n0 + wn * 64 + ni * 8 + ec;
            int bb = n >> 5, hh = n & 31;
            int bi = ni >> 2;
            if (r0 < Tsz) {
                float2 o = *(const float2*)&g_hsT[(size_t)r0 * NBH + n];
                float2 wf = *(const float2*)&Wfc[r0 * Hsz + hh];
                float2 v = make_float2(o.x * (acc[mi][ni][0] + bw0),
                                       o.y * (acc[mi][ni][1] + bw0));
                *(float2*)&qk_out[(size_t)bb * (Tsz * Hsz) + r0 * Hsz + hh] = v;
                pb[bi] = fmaf(v.x, wf.x, fmaf(v.y, wf.y, pb[bi]));
            }
            if (r1 < Tsz) {
                float2 o = *(const float2*)&g_hsT[(size_t)r1 * NBH + n];
                float2 wf = *(const float2*)&Wfc[r1 * Hsz + hh];
                float2 v = make_float2(o.x * (acc[mi][ni][2] + bw1),
                                       o.y * (acc[mi][ni][3] + bw1));
                *(float2*)&qk_out[(size_t)bb * (Tsz * Hsz) + r1 * Hsz + hh] = v;
                pb[bi] = fmaf(v.x, wf.x, fmaf(v.y, wf.y, pb[bi]));
            }
        }
    }
    redfc[(wn * 2 + 0) * 128 + wm * 32 + lane] = pb[0];
    redfc[(wn * 2 + 1) * 128 + wm * 32 + lane] = pb[1];
    __syncthreads();
    if (wid < 4) {
        float s = redfc[wid * 128 + lane] + redfc[wid * 128 + lane + 32]
                + redfc[wid * 128 + lane + 64] + redfc[wid * 128 + lane + 96];
#pragma unroll
        for (int o = 16; o > 0; o >>= 1) s += __shfl_xor_sync(0xffffffffu, s, o);
        if (lane == 0) g_fcpart[((n0 >> 5) + wid) * NMB + blockIdx.x] = s;
    }
}

// Final fc: out[b] = bfc + sum over 7 m-block partials
__global__ void fc_final(const float* __restrict__ bfc, float* __restrict__ fc_out) {
    int b = threadIdx.x;
    float s = bfc[0];
#pragma unroll
    for (int i = 0; i < NMB; i++) s += g_fcpart[b * NMB + i];
    fc_out[b] = s;
}

// ============================================================================
// Launcher
// ============================================================================
extern "C" void kernel_launch(void* const* d_in, const int* in_sizes, int n_in,
                              void* d_out, int out_size) {
    const float* x   = (const float*)d_in[0];
    const float* Wih = (const float*)d_in[1];
    const float* Whh = (const float*)d_in[2];
    const float* bih = (const float*)d_in[3];
    const float* bhh = (const float*)d_in[4];
    const float* Ww  = (const float*)d_in[5];
    const float* bw  = (const float*)d_in[6];
    const float* Wfc = (const float*)d_in[7];
    const float* bfc = (const float*)d_in[8];
    float* out = (float*)d_out;

    const long QK = (long)Bsz * Tsz * Hsz;
    float* fc_out;
    float* qk_out;
    if (out_size == (int)(QK + Bsz)) {
        fc_out = out;
        qk_out = out + Bsz;
    } else if (out_size == (int)QK) {
        qk_out = out;
        cudaGetSymbolAddress((void**)&fc_out, g_fc_scratch);
    } else {
        fc_out = out;
        cudaGetSymbolAddress((void**)&qk_out, g_qk_scratch);
    }

    // 0. one-time operand splits
    cvt_wih<<<(128 * IszP + 255) / 256, 256>>>(Wih);
    cvt_ww<<<(800 * 800 + 255) / 256, 256>>>(Ww);

    // 1. input projection GEMM (pipelined split-bf16)
    gemm_gx_mma<<<(Bsz * Tsz) / 128, 256>>>(x, bih, bhh);

    // 2. sequential LSTM scan — R12 structure + distance-8 static prefetch
    lstm_scan<<<Bsz, 128>>>(Whh);

    // 3. attention GEMM + fused qk/fc epilogue
    dim3 g2(NMB, NBH / 128);                 // (7, 32)
    gemm_q_mma<<<g2, 256>>>(bw, Wfc, qk_out);

    // 4. final fc reduction
    fc_final<<<1, Bsz>>>(bfc, fc_out);
}

// round 15
// speedup vs baseline: 1.8040x; 1.1630x over previous
#include <cuda_runtime.h>
#include <cuda_bf16.h>
#include <cstdint>

// Problem constants
#define Bsz 128          // batch
#define Tsz 800          // seq len
#define Isz 300          // input dim
#define IszP 304         // padded to 16
#define Hsz 32           // hidden
#define Gsz 128          // 4*H
#define NBH 4096         // B*H
#define NMB 7            // m-blocks in gemm_q (ceil(800/128))

// ---------------- scratch (static __device__, no runtime alloc) -------------
__device__ float g_gx[(size_t)Bsz * Tsz * Gsz];       // [B*T, 4H]  52.4 MB
__device__ float g_hsT[(size_t)Tsz * NBH];            // [T, B*H] fp32
__device__ __nv_bfloat16 g_hsT_hi[(size_t)Tsz * NBH]; // [T, B*H] bf16 hi
__device__ __nv_bfloat16 g_hsT_lo[(size_t)Tsz * NBH]; // [T, B*H] bf16 lo
__device__ __nv_bfloat16 g_Wih_hi[128 * IszP], g_Wih_lo[128 * IszP];
__device__ __nv_bfloat16 g_Ww_hi[800 * 800],  g_Ww_lo[800 * 800];
__device__ float g_fcpart[Bsz * NMB];                 // deterministic partials
__device__ float g_qk_scratch[(size_t)Bsz * Tsz * Hsz];
__device__ float g_fc_scratch[Bsz];

// ---------------- PTX helpers ----------------------------------------------
__device__ __forceinline__ uint32_t sptr(const void* p) {
    return (uint32_t)__cvta_generic_to_shared(p);
}
__device__ __forceinline__ void ldsm4(uint32_t* r, uint32_t a) {
    asm volatile("ldmatrix.sync.aligned.m8n8.x4.shared.b16 {%0,%1,%2,%3}, [%4];"
                 : "=r"(r[0]), "=r"(r[1]), "=r"(r[2]), "=r"(r[3]) : "r"(a));
}
__device__ __forceinline__ void ldsm4t(uint32_t* r, uint32_t a) {
    asm volatile("ldmatrix.sync.aligned.m8n8.x4.trans.shared.b16 {%0,%1,%2,%3}, [%4];"
                 : "=r"(r[0]), "=r"(r[1]), "=r"(r[2]), "=r"(r[3]) : "r"(a));
}
__device__ __forceinline__ void mma16816(float* d, const uint32_t* a, const uint32_t* b) {
    asm volatile(
        "mma.sync.aligned.m16n8k16.row.col.f32.bf16.bf16.f32 "
        "{%0,%1,%2,%3}, {%4,%5,%6,%7}, {%8,%9}, {%0,%1,%2,%3};"
        : "+f"(d[0]), "+f"(d[1]), "+f"(d[2]), "+f"(d[3])
        : "r"(a[0]), "r"(a[1]), "r"(a[2]), "r"(a[3]), "r"(b[0]), "r"(b[1]));
}

// Fast activations: div.approx (single MUFU.RCP) + EX2-based exp.
__device__ __forceinline__ float sigm_(float z) {
    return __fdividef(1.f, 1.f + __expf(-z));
}
__device__ __forceinline__ float tanh_(float z) {
    return fmaf(2.f, __fdividef(1.f, 1.f + __expf(-2.f * z)), -1.f);
}

// Split 8 fp32 -> bf16 hi/lo, one uint4 STS each.
__device__ __forceinline__ void cvt_store8(__nv_bfloat16* dhi, __nv_bfloat16* dlo,
                                           const float* v) {
    uint32_t hi[4], lo[4];
#pragma unroll
    for (int i = 0; i < 4; i++) {
        __nv_bfloat16 h0 = __float2bfloat16(v[2 * i]);
        __nv_bfloat16 h1 = __float2bfloat16(v[2 * i + 1]);
        __nv_bfloat16 l0 = __float2bfloat16(v[2 * i]     - __bfloat162float(h0));
        __nv_bfloat16 l1 = __float2bfloat16(v[2 * i + 1] - __bfloat162float(h1));
        __nv_bfloat162 hh = __halves2bfloat162(h0, h1);
        __nv_bfloat162 ll = __halves2bfloat162(l0, l1);
        hi[i] = *reinterpret_cast<uint32_t*>(&hh);
        lo[i] = *reinterpret_cast<uint32_t*>(&ll);
    }
    *reinterpret_cast<uint4*>(dhi) = make_uint4(hi[0], hi[1], hi[2], hi[3]);
    *reinterpret_cast<uint4*>(dlo) = make_uint4(lo[0], lo[1], lo[2], lo[3]);
}

// ---------------- prep: one-time fp32 -> bf16 hi/lo splits ------------------
__global__ __launch_bounds__(256) void cvt_wih(const float* __restrict__ W) {
    int i = blockIdx.x * 256 + threadIdx.x;
    if (i >= 128 * IszP) return;
    int r = i / IszP, c = i - r * IszP;
    float v = (c < Isz) ? W[r * Isz + c] : 0.f;
    __nv_bfloat16 h = __float2bfloat16(v);
    g_Wih_hi[i] = h;
    g_Wih_lo[i] = __float2bfloat16(v - __bfloat162float(h));
}
__global__ __launch_bounds__(256) void cvt_ww(const float* __restrict__ W) {
    int i = blockIdx.x * 256 + threadIdx.x;
    if (i >= 800 * 800) return;
    float v = W[i];
    __nv_bfloat16 h = __float2bfloat16(v);
    g_Ww_hi[i] = h;
    g_Ww_lo[i] = __float2bfloat16(v - __bfloat162float(h));
}

// ============================================================================
// Kernel 1: gx = x @ W_ih^T + (b_ih + b_hh), split-bf16 HMMA, pipelined.
// ============================================================================
#define APAD 24
#define NIT1 (IszP / 16)     // 19
__global__ __launch_bounds__(256, 2) void gemm_gx_mma(
    const float* __restrict__ X,
    const float* __restrict__ bih, const float* __restrict__ bhh) {
    __shared__ __align__(16) __nv_bfloat16 sAhi[2][128 * APAD], sAlo[2][128 * APAD];
    __shared__ __align__(16) __nv_bfloat16 sBhi[2][128 * APAD], sBlo[2][128 * APAD];

    const int m0   = blockIdx.x * 128;
    const int tid  = threadIdx.x;
    const int lane = tid & 31;
    const int wid  = tid >> 5;
    const int wm   = wid >> 1;
    const int wn   = wid & 1;

    float acc[2][8][4];
#pragma unroll
    for (int mi = 0; mi < 2; mi++)
#pragma unroll
        for (int ni = 0; ni < 8; ni++)
#pragma unroll
            for (int e = 0; e < 4; e++) acc[mi][ni][e] = 0.f;

    const int lr = tid >> 1;
    const int lk = (tid & 1) * 8;

    const int amrow = lane & 15;
    const int akcol = (lane >> 4) * 8;
    int offA[2];
#pragma unroll
    for (int mi = 0; mi < 2; mi++)
        offA[mi] = (wm * 32 + mi * 16 + amrow) * APAD + akcol;
    const int bnrow = (lane & 7) + ((lane & 16) >> 1);
    const int bkcol = (lane & 8) ? 8 : 0;
    int offB[4];
#pragma unroll
    for (int nb = 0; nb < 4; nb++)
        offB[nb] = (wn * 64 + nb * 16 + bnrow) * APAD + bkcol;

    float va[8];
    uint4 pbh, pbl;

    auto loadA = [&](int k0) {
        if (k0 + lk + 7 < Isz) {
            *(float4*)&va[0] = *(const float4*)&X[(size_t)(m0 + lr) * Isz + k0 + lk];
            *(float4*)&va[4] = *(const float4*)&X[(size_t)(m0 + lr) * Isz + k0 + lk + 4];
        } else {
#pragma unroll
            for (int j = 0; j < 8; j++) {
                int k = k0 + lk + j;
                va[j] = (k < Isz) ? X[(size_t)(m0 + lr) * Isz + k] : 0.f;
            }
        }
    };
    auto loadB = [&](int k0) {
        pbh = *(const uint4*)&g_Wih_hi[lr * IszP + k0 + lk];
        pbl = *(const uint4*)&g_Wih_lo[lr * IszP + k0 + lk];
    };
    auto stA = [&](int buf) {
        cvt_store8(&sAhi[buf][lr * APAD + lk], &sAlo[buf][lr * APAD + lk], va);
    };
    auto stB = [&](int buf) {
        *(uint4*)&sBhi[buf][lr * APAD + lk] = pbh;
        *(uint4*)&sBlo[buf][lr * APAD + lk] = pbl;
    };

    loadA(0); loadB(0);
    stA(0); stB(0);
    __syncthreads();

#pragma unroll 1
    for (int it = 0; it < NIT1; it++) {
        const int cur = it & 1;
        const bool more = (it + 1 < NIT1);
        if (more) { loadA((it + 1) * 16); loadB((it + 1) * 16); }

        uint32_t afr[2][4], alo[2][4], bfr[8][2];
        ldsm4(afr[0], sptr(&sAhi[cur][offA[0]]));
        ldsm4(afr[1], sptr(&sAhi[cur][offA[1]]));
#pragma unroll
        for (int nb = 0; nb < 4; nb++) {
            uint32_t r[4];
            ldsm4(r, sptr(&sBhi[cur][offB[nb]]));
            bfr[2 * nb][0] = r[0]; bfr[2 * nb][1] = r[1];
            bfr[2 * nb + 1][0] = r[2]; bfr[2 * nb + 1][1] = r[3];
        }
#pragma unroll
        for (int mi = 0; mi < 2; mi++)
#pragma unroll
            for (int ni = 0; ni < 8; ni++) mma16816(acc[mi][ni], afr[mi], bfr[ni]);

        ldsm4(alo[0], sptr(&sAlo[cur][offA[0]]));
        ldsm4(alo[1], sptr(&sAlo[cur][offA[1]]));
#pragma unroll
        for (int mi = 0; mi < 2; mi++)
#pragma unroll
            for (int ni = 0; ni < 8; ni++) mma16816(acc[mi][ni], alo[mi], bfr[ni]);

#pragma unroll
        for (int nb = 0; nb < 4; nb++) {
            uint32_t r[4];
            ldsm4(r, sptr(&sBlo[cur][offB[nb]]));
            bfr[2 * nb][0] = r[0]; bfr[2 * nb][1] = r[1];
            bfr[2 * nb + 1][0] = r[2]; bfr[2 * nb + 1][1] = r[3];
        }
#pragma unroll
        for (int mi = 0; mi < 2; mi++)
#pragma unroll
            for (int ni = 0; ni < 8; ni++) mma16816(acc[mi][ni], afr[mi], bfr[ni]);

        if (more) { stA(cur ^ 1); stB(cur ^ 1); }
        __syncthreads();
    }

    const int er = lane >> 2;
    const int ec = (lane & 3) * 2;
    float bias0[8], bias1[8];
#pragma unroll
    for (int ni = 0; ni < 8; ni++) {
        int col = wn * 64 + ni * 8 + ec;
        bias0[ni] = bih[col] + bhh[col];
        bias1[ni] = bih[col + 1] + bhh[col + 1];
    }
#pragma unroll
    for (int mi = 0; mi < 2; mi++) {
        int row = m0 + wm * 32 + mi * 16 + er;
#pragma unroll
        for (int ni = 0; ni < 8; ni++) {
            int col = wn * 64 + ni * 8 + ec;
            float2 v0 = make_float2(acc[mi][ni][0] + bias0[ni], acc[mi][ni][1] + bias1[ni]);
            float2 v1 = make_float2(acc[mi][ni][2] + bias0[ni], acc[mi][ni][3] + bias1[ni]);
            *(float2*)&g_gx[(size_t)row * Gsz + col]       = v0;
            *(float2*)&g_gx[(size_t)(row + 8) * Gsz + col] = v1;
        }
    }
}

// ============================================================================
// Kernel 2: LSTM recurrence — R14 structure + LDS-based h exchange (replaces
// the 32-SHFL/warp/step broadcast, which saturated the shared MIO pipe:
// 4 warps x 32 SHFL x 128B >> 9 L1 wavefronts for 1 STS.32 + 8 broadcast
// LDS.128). Each warp keeps a PRIVATE smem h copy (its own lanes write it,
// __syncwarp orders, next step reads it broadcast). hsT stores + bf16
// converts distributed across warps 0/1/3 (all warps compute identical h)
// to kill warp-0 barrier skew. Distance-8 static gx ring kept from R14.
// ============================================================================
__global__ __launch_bounds__(128) void lstm_scan(const float* __restrict__ Whh) {
    const int b    = blockIdx.x;
    const int j    = threadIdx.x;
    const int lane = j & 31;
    const int wid  = j >> 5;
    __shared__ __align__(16) float sh_act[2][Gsz];   // [buf][unit*4 + gate]
    __shared__ __align__(16) float sh_h[4][Hsz];     // per-warp private h

    float w[Hsz];
#pragma unroll
    for (int k = 0; k < Hsz; k++) w[k] = Whh[j * Hsz + k];

    float c = 0.f, h = 0.f;
    sh_h[wid][lane] = 0.f;
    __syncwarp();

    const float* gxb = g_gx + (size_t)b * Tsz * Gsz;

    // distance-8 prefetch ring (static registers)
    float gq[8];
#pragma unroll
    for (int k = 0; k < 8; k++) gq[k] = gxb[(size_t)k * Gsz + j];

    const bool is_g = (wid == 2);

#pragma unroll 1
    for (int tt = 0; tt < Tsz; tt += 8) {
#pragma unroll
        for (int k = 0; k < 8; k++) {
            const int t = tt + k;
            float gcur = gq[k];
            if (t + 8 < Tsz) gq[k] = gxb[(size_t)(t + 8) * Gsz + j];

            // h vector from this warp's private smem: 8 broadcast LDS.128
            float hv[Hsz];
#pragma unroll
            for (int q = 0; q < Hsz / 4; q++)
                *(float4*)&hv[q * 4] = *(const float4*)&sh_h[wid][q * 4];

            // z = gx + W_hh[j,:] . h  (4-way split chains)
            float s0 = gcur, s1 = 0.f, s2 = 0.f, s3 = 0.f;
#pragma unroll
            for (int q = 0; q < Hsz; q += 4) {
                s0 = fmaf(w[q],     hv[q],     s0);
                s1 = fmaf(w[q + 1], hv[q + 1], s1);
                s2 = fmaf(w[q + 2], hv[q + 2], s2);
                s3 = fmaf(w[q + 3], hv[q + 3], s3);
            }
            float z = (s0 + s1) + (s2 + s3);

            float a = is_g ? tanh_(z) : sigm_(z);
            sh_act[k & 1][lane * 4 + wid] = a;
            __syncthreads();

            float4 g4 = *(const float4*)&sh_act[k & 1][lane * 4];  // (i,f,g,o)
            c = fmaf(g4.y, c, g4.x * g4.z);
            h = g4.w * tanh_(c);

            // private h for next step (own warp region; syncwarp orders)
            sh_h[wid][lane] = h;

            // distributed global stores (all warps hold identical h)
            size_t idx = (size_t)t * NBH + b * Hsz + lane;
            if (wid == 0) {
                g_hsT[idx] = h;
            } else if (wid == 1) {
                g_hsT_hi[idx] = __float2bfloat16(h);
            } else if (wid == 3) {
                __nv_bfloat16 hh = __float2bfloat16(h);
                g_hsT_lo[idx] = __float2bfloat16(h - __bfloat162float(hh));
            }
            __syncwarp();
        }
    }
}

// ============================================================================
// Kernel 3: attention GEMM + fused qk/fc epilogue (unchanged)
// ============================================================================
#define BPAD 136
#define NIT2 (Tsz / 16)      // 50
__global__ __launch_bounds__(256, 2) void gemm_q_mma(
    const float* __restrict__ bw, const float* __restrict__ Wfc,
    float* __restrict__ qk_out) {
    __shared__ __align__(16) __nv_bfloat16 sAhi[2][128 * APAD], sAlo[2][128 * APAD];
    __shared__ __align__(16) __nv_bfloat16 sBhi[2][16 * BPAD],  sBlo[2][16 * BPAD];
    __shared__ float redfc[512];

    const int m0   = blockIdx.x * 128;
    const int n0   = blockIdx.y * 128;
    const int tid  = threadIdx.x;
    const int lane = tid & 31;
    const int wid  = tid >> 5;
    const int wm   = wid >> 1;
    const int wn   = wid & 1;

    float acc[2][8][4];
#pragma unroll
    for (int mi = 0; mi < 2; mi++)
#pragma unroll
        for (int ni = 0; ni < 8; ni++)
#pragma unroll
            for (int e = 0; e < 4; e++) acc[mi][ni][e] = 0.f;

    const int alr = tid >> 1;
    const int alk = (tid & 1) * 8;
    const int blr = tid >> 4;
    const int bln = (tid & 15) * 8;
    const bool arow_ok = (m0 + alr < Tsz);

    const int amrow = lane & 15;
    const int akcol = (lane >> 4) * 8;
    int offA[2];
#pragma unroll
    for (int mi = 0; mi < 2; mi++)
        offA[mi] = (wm * 32 + mi * 16 + amrow) * APAD + akcol;
    const int qbrow = lane & 15;
    const int qbcol = (lane >> 4) * 8;
    int offB[4];
#pragma unroll
    for (int nb = 0; nb < 4; nb++)
        offB[nb] = qbrow * BPAD + wn * 64 + nb * 16 + qbcol;

    uint4 pah, pal, pbh, pbl;
    auto loadA = [&](int k0) {
        if (arow_ok) {
            pah = *(const uint4*)&g_Ww_hi[(size_t)(m0 + alr) * Tsz + k0 + alk];
            pal = *(const uint4*)&g_Ww_lo[(size_t)(m0 + alr) * Tsz + k0 + alk];
        } else {
            pah = make_uint4(0, 0, 0, 0);
            pal = make_uint4(0, 0, 0, 0);
        }
    };
    auto loadB = [&](int k0) {
        pbh = *(const uint4*)&g_hsT_hi[(size_t)(k0 + blr) * NBH + n0 + bln];
        pbl = *(const uint4*)&g_hsT_lo[(size_t)(k0 + blr) * NBH + n0 + bln];
    };
    auto stA = [&](int buf) {
        *(uint4*)&sAhi[buf][alr * APAD + alk] = pah;
        *(uint4*)&sAlo[buf][alr * APAD + alk] = pal;
    };
    auto stB = [&](int buf) {
        *(uint4*)&sBhi[buf][blr * BPAD + bln] = pbh;
        *(uint4*)&sBlo[buf][blr * BPAD + bln] = pbl;
    };

    loadA(0); loadB(0);
    stA(0); stB(0);
    __syncthreads();

#pragma unroll 1
    for (int it = 0; it < NIT2; it++) {
        const int cur = it & 1;
        const bool more = (it + 1 < NIT2);
        if (more) { loadA((it + 1) * 16); loadB((it + 1) * 16); }

        uint32_t afr[2][4], alo2[2][4], bfr[8][2];
        ldsm4(afr[0], sptr(&sAhi[cur][offA[0]]));
        ldsm4(afr[1], sptr(&sAhi[cur][offA[1]]));
#pragma unroll
        for (int nb = 0; nb < 4; nb++) {
            uint32_t r[4];
            ldsm4t(r, sptr(&sBhi[cur][offB[nb]]));
            bfr[2 * nb][0] = r[0]; bfr[2 * nb][1] = r[1];
            bfr[2 * nb + 1][0] = r[2]; bfr[2 * nb + 1][1] = r[3];
        }
#pragma unroll
        for (int mi = 0; mi < 2; mi++)
#pragma unroll
            for (int ni = 0; ni < 8; ni++) mma16816(acc[mi][ni], afr[mi], bfr[ni]);

        ldsm4(alo2[0], sptr(&sAlo[cur][offA[0]]));
        ldsm4(alo2[1], sptr(&sAlo[cur][offA[1]]));
#pragma unroll
        for (int mi = 0; mi < 2; mi++)
#pragma unroll
            for (int ni = 0; ni < 8; ni++) mma16816(acc[mi][ni], alo2[mi], bfr[ni]);

#pragma unroll
        for (int nb = 0; nb < 4; nb++) {
            uint32_t r[4];
            ldsm4t(r, sptr(&sBlo[cur][offB[nb]]));
            bfr[2 * nb][0] = r[0]; bfr[2 * nb][1] = r[1];
            bfr[2 * nb + 1][0] = r[2]; bfr[2 * nb + 1][1] = r[3];
        }
#pragma unroll
        for (int mi = 0; mi < 2; mi++)
#pragma unroll
            for (int ni = 0; ni < 8; ni++) mma16816(acc[mi][ni], afr[mi], bfr[ni]);

        if (more) { stA(cur ^ 1); stB(cur ^ 1); }
        __syncthreads();
    }

    // ---- fused epilogue: qk = hsT*(q+bw), fc partials ----
    const int er = lane >> 2;
    const int ec = (lane & 3) * 2;
    float pb[2] = {0.f, 0.f};
#pragma unroll
    for (int mi = 0; mi < 2; mi++) {
        int r0 = m0 + wm * 32 + mi * 16 + er;
        int r1 = r0 + 8;
        float bw0 = (r0 < Tsz) ? bw[r0] : 0.f;
        float bw1 = (r1 < Tsz) ? bw[r1] : 0.f;
#pragma unroll
        for (int ni = 0; ni < 8; ni++) {
            int n  = n0 + wn * 64 + ni * 8 + ec;
            int bb = n >> 5, hh = n & 31;
            int bi = ni >> 2;
            if (r0 < Tsz) {
                float2 o = *(const float2*)&g_hsT[(size_t)r0 * NBH + n];
                float2 wf = *(const float2*)&Wfc[r0 * Hsz + hh];
                float2 v = make_float2(o.x * (acc[mi][ni][0] + bw0),
                                       o.y * (acc[mi][ni][1] + bw0));
                *(float2*)&qk_out[(size_t)bb * (Tsz * Hsz) + r0 * Hsz + hh] = v;
                pb[bi] = fmaf(v.x, wf.x, fmaf(v.y, wf.y, pb[bi]));
            }
            if (r1 < Tsz) {
                float2 o = *(const float2*)&g_hsT[(size_t)r1 * NBH + n];
                float2 wf = *(const float2*)&Wfc[r1 * Hsz + hh];
                float2 v = make_float2(o.x * (acc[mi][ni][2] + bw1),
                                       o.y * (acc[mi][ni][3] + bw1));
                *(float2*)&qk_out[(size_t)bb * (Tsz * Hsz) + r1 * Hsz + hh] = v;
                pb[bi] = fmaf(v.x, wf.x, fmaf(v.y, wf.y, pb[bi]));
            }
        }
    }
    redfc[(wn * 2 + 0) * 128 + wm * 32 + lane] = pb[0];
    redfc[(wn * 2 + 1) * 128 + wm * 32 + lane] = pb[1];
    __syncthreads();
    if (wid < 4) {
        float s = redfc[wid * 128 + lane] + redfc[wid * 128 + lane + 32]
                + redfc[wid * 128 + lane + 64] + redfc[wid * 128 + lane + 96];
#pragma unroll
        for (int o = 16; o > 0; o >>= 1) s += __shfl_xor_sync(0xffffffffu, s, o);
        if (lane == 0) g_fcpart[((n0 >> 5) + wid) * NMB + blockIdx.x] = s;
    }
}

// Final fc: out[b] = bfc + sum over 7 m-block partials
__global__ void fc_final(const float* __restrict__ bfc, float* __restrict__ fc_out) {
    int b = threadIdx.x;
    float s = bfc[0];
#pragma unroll
    for (int i = 0; i < NMB; i++) s += g_fcpart[b * NMB + i];
    fc_out[b] = s;
}

// ============================================================================
// Launcher
// ============================================================================
extern "C" void kernel_launch(void* const* d_in, const int* in_sizes, int n_in,
                              void* d_out, int out_size) {
    const float* x   = (const float*)d_in[0];
    const float* Wih = (const float*)d_in[1];
    const float* Whh = (const float*)d_in[2];
    const float* bih = (const float*)d_in[3];
    const float* bhh = (const float*)d_in[4];
    const float* Ww  = (const float*)d_in[5];
    const float* bw  = (const float*)d_in[6];
    const float* Wfc = (const float*)d_in[7];
    const float* bfc = (const float*)d_in[8];
    float* out = (float*)d_out;

    const long QK = (long)Bsz * Tsz * Hsz;
    float* fc_out;
    float* qk_out;
    if (out_size == (int)(QK + Bsz)) {
        fc_out = out;
        qk_out = out + Bsz;
    } else if (out_size == (int)QK) {
        qk_out = out;
        cudaGetSymbolAddress((void**)&fc_out, g_fc_scratch);
    } else {
        fc_out = out;
        cudaGetSymbolAddress((void**)&qk_out, g_qk_scratch);
    }

    // 0. one-time operand splits
    cvt_wih<<<(128 * IszP + 255) / 256, 256>>>(Wih);
    cvt_ww<<<(800 * 800 + 255) / 256, 256>>>(Ww);

    // 1. input projection GEMM (pipelined split-bf16)
    gemm_gx_mma<<<(Bsz * Tsz) / 128, 256>>>(x, bih, bhh);

    // 2. sequential LSTM scan — LDS h exchange + static ring + store spread
    lstm_scan<<<Bsz, 128>>>(Whh);

    // 3. attention GEMM + fused qk/fc epilogue
    dim3 g2(NMB, NBH / 128);                 // (7, 32)
    gemm_q_mma<<<g2, 256>>>(bw, Wfc, qk_out);

    // 4. final fc reduction
    fc_final<<<1, Bsz>>>(bfc, fc_out);
}

// round 16
// speedup vs baseline: 1.8111x; 1.0039x over previous
#include <cuda_runtime.h>
#include <cuda_bf16.h>
#include <cstdint>

// Problem constants
#define Bsz 128          // batch
#define Tsz 800          // seq len
#define Isz 300          // input dim
#define IszP 304         // padded to 16
#define Hsz 32           // hidden
#define Gsz 128          // 4*H
#define NBH 4096         // B*H
#define NMB 7            // m-blocks in gemm_q (ceil(800/128))

// ---------------- scratch (static __device__, no runtime alloc) -------------
__device__ float g_gx[(size_t)Bsz * Tsz * Gsz];       // [B*T, 4H]  52.4 MB
__device__ float g_hsT[(size_t)Tsz * NBH];            // [T, B*H] fp32
__device__ __nv_bfloat16 g_hsT_hi[(size_t)Tsz * NBH]; // [T, B*H] bf16 hi
__device__ __nv_bfloat16 g_hsT_lo[(size_t)Tsz * NBH]; // [T, B*H] bf16 lo
__device__ __nv_bfloat16 g_Wih_hi[128 * IszP], g_Wih_lo[128 * IszP];
__device__ __nv_bfloat16 g_Ww_hi[800 * 800],  g_Ww_lo[800 * 800];
__device__ float g_fcpart[Bsz * NMB];                 // deterministic partials
__device__ float g_qk_scratch[(size_t)Bsz * Tsz * Hsz];
__device__ float g_fc_scratch[Bsz];

// ---------------- PTX helpers ----------------------------------------------
__device__ __forceinline__ uint32_t sptr(const void* p) {
    return (uint32_t)__cvta_generic_to_shared(p);
}
__device__ __forceinline__ void ldsm4(uint32_t* r, uint32_t a) {
    asm volatile("ldmatrix.sync.aligned.m8n8.x4.shared.b16 {%0,%1,%2,%3}, [%4];"
                 : "=r"(r[0]), "=r"(r[1]), "=r"(r[2]), "=r"(r[3]) : "r"(a));
}
__device__ __forceinline__ void ldsm4t(uint32_t* r, uint32_t a) {
    asm volatile("ldmatrix.sync.aligned.m8n8.x4.trans.shared.b16 {%0,%1,%2,%3}, [%4];"
                 : "=r"(r[0]), "=r"(r[1]), "=r"(r[2]), "=r"(r[3]) : "r"(a));
}
__device__ __forceinline__ void mma16816(float* d, const uint32_t* a, const uint32_t* b) {
    asm volatile(
        "mma.sync.aligned.m16n8k16.row.col.f32.bf16.bf16.f32 "
        "{%0,%1,%2,%3}, {%4,%5,%6,%7}, {%8,%9}, {%0,%1,%2,%3};"
        : "+f"(d[0]), "+f"(d[1]), "+f"(d[2]), "+f"(d[3])
        : "r"(a[0]), "r"(a[1]), "r"(a[2]), "r"(a[3]), "r"(b[0]), "r"(b[1]));
}

#define BARSYNC(id, n) asm volatile("bar.sync %0, %1;" :: "r"(id), "r"(n) : "memory")

// Fast activations: div.approx (single MUFU.RCP) + EX2-based exp.
__device__ __forceinline__ float sigm_(float z) {
    return __fdividef(1.f, 1.f + __expf(-z));
}
__device__ __forceinline__ float tanh_(float z) {
    return fmaf(2.f, __fdividef(1.f, 1.f + __expf(-2.f * z)), -1.f);
}

// Split 8 fp32 -> bf16 hi/lo, one uint4 STS each.
__device__ __forceinline__ void cvt_store8(__nv_bfloat16* dhi, __nv_bfloat16* dlo,
                                           const float* v) {
    uint32_t hi[4], lo[4];
#pragma unroll
    for (int i = 0; i < 4; i++) {
        __nv_bfloat16 h0 = __float2bfloat16(v[2 * i]);
        __nv_bfloat16 h1 = __float2bfloat16(v[2 * i + 1]);
        __nv_bfloat16 l0 = __float2bfloat16(v[2 * i]     - __bfloat162float(h0));
        __nv_bfloat16 l1 = __float2bfloat16(v[2 * i + 1] - __bfloat162float(h1));
        __nv_bfloat162 hh = __halves2bfloat162(h0, h1);
        __nv_bfloat162 ll = __halves2bfloat162(l0, l1);
        hi[i] = *reinterpret_cast<uint32_t*>(&hh);
        lo[i] = *reinterpret_cast<uint32_t*>(&ll);
    }
    *reinterpret_cast<uint4*>(dhi) = make_uint4(hi[0], hi[1], hi[2], hi[3]);
    *reinterpret_cast<uint4*>(dlo) = make_uint4(lo[0], lo[1], lo[2], lo[3]);
}

// ---------------- prep: one-time fp32 -> bf16 hi/lo splits ------------------
__global__ __launch_bounds__(256) void cvt_wih(const float* __restrict__ W) {
    int i = blockIdx.x * 256 + threadIdx.x;
    if (i >= 128 * IszP) return;
    int r = i / IszP, c = i - r * IszP;
    float v = (c < Isz) ? W[r * Isz + c] : 0.f;
    __nv_bfloat16 h = __float2bfloat16(v);
    g_Wih_hi[i] = h;
    g_Wih_lo[i] = __float2bfloat16(v - __bfloat162float(h));
}
__global__ __launch_bounds__(256) void cvt_ww(const float* __restrict__ W) {
    int i = blockIdx.x * 256 + threadIdx.x;
    if (i >= 800 * 800) return;
    float v = W[i];
    __nv_bfloat16 h = __float2bfloat16(v);
    g_Ww_hi[i] = h;
    g_Ww_lo[i] = __float2bfloat16(v - __bfloat162float(h));
}

// ============================================================================
// FUSED kernel: gx GEMM (producer, warps 4-7) + LSTM scan (consumer, warps
// 0-3), one CTA per batch element. Producer computes gx[b] in 7 chunks of
// 128 timesteps (two 64x128 half-tiles, split-bf16 HMMA) and stays one chunk
// ahead of the consumer via named barrier 1 (count 256, BOTH sides blocking
// bar.sync -> phase-locked, deadlock-free). Consumer = R15 lstm (LDS h
// exchange, distance-8 static gx ring, distributed hsT stores) with its
// per-step sync on named barrier 2 (count 128). Producer k-loop syncs on
// barrier 4 (count 128).
// ============================================================================
#define APAD 24
#define NIT1 (IszP / 16)     // 19
__global__ __launch_bounds__(256, 1) void gx_lstm_fused(
    const float* __restrict__ X,   const float* __restrict__ Whh,
    const float* __restrict__ bih, const float* __restrict__ bhh) {
    const int b    = blockIdx.x;
    const int tid  = threadIdx.x;
    const int lane = tid & 31;
    const int wid  = tid >> 5;

    // producer smem (A: 64 rows, B: 128 rows; double-buffered hi/lo)
    __shared__ __align__(16) __nv_bfloat16 sAhi[2][64 * APAD],  sAlo[2][64 * APAD];
    __shared__ __align__(16) __nv_bfloat16 sBhi[2][128 * APAD], sBlo[2][128 * APAD];
    // consumer smem
    __shared__ __align__(16) float sh_act[2][Gsz];   // [buf][unit*4 + gate]
    __shared__ __align__(16) float sh_h[4][Hsz];     // per-warp private h

    if (wid < 4) {
        // ==================== CONSUMER: LSTM ====================
        const int j = tid;               // gate row 0..127
        float w[Hsz];
#pragma unroll
        for (int k = 0; k < Hsz; k++) w[k] = Whh[j * Hsz + k];

        float c = 0.f, h = 0.f;
        sh_h[wid][lane] = 0.f;
        __syncwarp();

        const float* gxb = g_gx + (size_t)b * Tsz * Gsz;
        const bool is_g = (wid == 2);

        BARSYNC(1, 256);                 // wait for chunk 0

        float gq[8];
#pragma unroll
        for (int k = 0; k < 8; k++) gq[k] = gxb[(size_t)k * Gsz + j];

#pragma unroll 1
        for (int tt = 0; tt < Tsz; tt += 8) {
            if ((tt & 127) == 120) BARSYNC(1, 256);   // next chunk ready
#pragma unroll
            for (int k = 0; k < 8; k++) {
                const int t = tt + k;
                float gcur = gq[k];
                if (t + 8 < Tsz) gq[k] = gxb[(size_t)(t + 8) * Gsz + j];

                float hv[Hsz];
#pragma unroll
                for (int q = 0; q < Hsz / 4; q++)
                    *(float4*)&hv[q * 4] = *(const float4*)&sh_h[wid][q * 4];

                float s0 = gcur, s1 = 0.f, s2 = 0.f, s3 = 0.f;
#pragma unroll
                for (int q = 0; q < Hsz; q += 4) {
                    s0 = fmaf(w[q],     hv[q],     s0);
                    s1 = fmaf(w[q + 1], hv[q + 1], s1);
                    s2 = fmaf(w[q + 2], hv[q + 2], s2);
                    s3 = fmaf(w[q + 3], hv[q + 3], s3);
                }
                float z = (s0 + s1) + (s2 + s3);

                float a = is_g ? tanh_(z) : sigm_(z);
                sh_act[k & 1][lane * 4 + wid] = a;
                BARSYNC(2, 128);

                float4 g4 = *(const float4*)&sh_act[k & 1][lane * 4];
                c = fmaf(g4.y, c, g4.x * g4.z);
                h = g4.w * tanh_(c);

                sh_h[wid][lane] = h;

                size_t idx = (size_t)t * NBH + b * Hsz + lane;
                if (wid == 0) {
                    g_hsT[idx] = h;
                } else if (wid == 1) {
                    g_hsT_hi[idx] = __float2bfloat16(h);
                } else if (wid == 3) {
                    __nv_bfloat16 hh = __float2bfloat16(h);
                    g_hsT_lo[idx] = __float2bfloat16(h - __bfloat162float(hh));
                }
                __syncwarp();
            }
        }
    } else {
        // ==================== PRODUCER: gx GEMM ====================
        const int ptid = tid - 128;      // 0..127
        const int pw   = wid - 4;        // 0..3
        const int wm   = pw >> 1;        // 0..1 (M half of 64)
        const int wn   = pw & 1;         // 0..1 (N half of 128)

        const int alr = ptid >> 1;       // A row 0..63
        const int alk = (ptid & 1) * 8;
        const int brow = ptid;           // Wih row 0..127

        const int amrow = lane & 15;
        const int akcol = (lane >> 4) * 8;
        int offA[2];
#pragma unroll
        for (int mi = 0; mi < 2; mi++)
            offA[mi] = (wm * 32 + mi * 16 + amrow) * APAD + akcol;
        const int bnrow = (lane & 7) + ((lane & 16) >> 1);
        const int bkcol = (lane & 8) ? 8 : 0;
        int offB[4];
#pragma unroll
        for (int nb = 0; nb < 4; nb++)
            offB[nb] = (wn * 64 + nb * 16 + bnrow) * APAD + bkcol;

        const int er = lane >> 2;
        const int ec = (lane & 3) * 2;
        float bias0[8], bias1[8];
#pragma unroll
        for (int ni = 0; ni < 8; ni++) {
            int col = wn * 64 + ni * 8 + ec;
            bias0[ni] = bih[col] + bhh[col];
            bias1[ni] = bih[col + 1] + bhh[col + 1];
        }

        const float* Xb = X + (size_t)b * Tsz * Isz;

        float va[8];
        uint4 pbh0, pbh1, pbl0, pbl1;

#pragma unroll 1
        for (int ch = 0; ch < 7; ch++) {
#pragma unroll 1
            for (int hm = 0; hm < 2; hm++) {
                const int t0 = ch * 128 + hm * 64;
                if (t0 >= Tsz) continue;             // uniform skip (ch=6,hm=1)

                float acc[2][8][4];
#pragma unroll
                for (int mi = 0; mi < 2; mi++)
#pragma unroll
                    for (int ni = 0; ni < 8; ni++)
#pragma unroll
                        for (int e = 0; e < 4; e++) acc[mi][ni][e] = 0.f;

                auto loadA = [&](int k0) {
                    int trow = t0 + alr;
                    if (trow < Tsz && k0 + alk + 7 < Isz) {
                        const float* xr = Xb + (size_t)trow * Isz + k0 + alk;
                        *(float4*)&va[0] = *(const float4*)xr;
                        *(float4*)&va[4] = *(const float4*)(xr + 4);
                    } else {
#pragma unroll
                        for (int q = 0; q < 8; q++) {
                            int kk = k0 + alk + q;
                            va[q] = (trow < Tsz && kk < Isz)
                                        ? Xb[(size_t)trow * Isz + kk] : 0.f;
                        }
                    }
                };
                auto loadB = [&](int k0) {
                    pbh0 = *(const uint4*)&g_Wih_hi[brow * IszP + k0];
                    pbh1 = *(const uint4*)&g_Wih_hi[brow * IszP + k0 + 8];
                    pbl0 = *(const uint4*)&g_Wih_lo[brow * IszP + k0];
                    pbl1 = *(const uint4*)&g_Wih_lo[brow * IszP + k0 + 8];
                };
                auto stA = [&](int buf) {
                    cvt_store8(&sAhi[buf][alr * APAD + alk],
                               &sAlo[buf][alr * APAD + alk], va);
                };
                auto stB = [&](int buf) {
                    *(uint4*)&sBhi[buf][brow * APAD]     = pbh0;
                    *(uint4*)&sBhi[buf][brow * APAD + 8] = pbh1;
                    *(uint4*)&sBlo[buf][brow * APAD]     = pbl0;
                    *(uint4*)&sBlo[buf][brow * APAD + 8] = pbl1;
                };

                loadA(0); loadB(0);
                stA(0); stB(0);
                BARSYNC(4, 128);

#pragma unroll 1
                for (int it = 0; it < NIT1; it++) {
                    const int cur = it & 1;
                    const bool more = (it + 1 < NIT1);
                    if (more) { loadA((it + 1) * 16); loadB((it + 1) * 16); }

                    uint32_t afr[2][4], alo2[2][4], bfr[8][2];
                    ldsm4(afr[0], sptr(&sAhi[cur][offA[0]]));
                    ldsm4(afr[1], sptr(&sAhi[cur][offA[1]]));
#pragma unroll
                    for (int nb = 0; nb < 4; nb++) {
                        uint32_t r[4];
                        ldsm4(r, sptr(&sBhi[cur][offB[nb]]));
                        bfr[2 * nb][0] = r[0]; bfr[2 * nb][1] = r[1];
                        bfr[2 * nb + 1][0] = r[2]; bfr[2 * nb + 1][1] = r[3];
                    }
#pragma unroll
                    for (int mi = 0; mi < 2; mi++)
#pragma unroll
                        for (int ni = 0; ni < 8; ni++)
                            mma16816(acc[mi][ni], afr[mi], bfr[ni]);

                    ldsm4(alo2[0], sptr(&sAlo[cur][offA[0]]));
                    ldsm4(alo2[1], sptr(&sAlo[cur][offA[1]]));
#pragma unroll
                    for (int mi = 0; mi < 2; mi++)
#pragma unroll
                        for (int ni = 0; ni < 8; ni++)
                            mma16816(acc[mi][ni], alo2[mi], bfr[ni]);

#pragma unroll
                    for (int nb = 0; nb < 4; nb++) {
                        uint32_t r[4];
                        ldsm4(r, sptr(&sBlo[cur][offB[nb]]));
                        bfr[2 * nb][0] = r[0]; bfr[2 * nb][1] = r[1];
                        bfr[2 * nb + 1][0] = r[2]; bfr[2 * nb + 1][1] = r[3];
                    }
#pragma unroll
                    for (int mi = 0; mi < 2; mi++)
#pragma unroll
                        for (int ni = 0; ni < 8; ni++)
                            mma16816(acc[mi][ni], afr[mi], bfr[ni]);

                    if (more) { stA(cur ^ 1); stB(cur ^ 1); }
                    BARSYNC(4, 128);
                }

                // epilogue: bias + guarded stores
#pragma unroll
                for (int mi = 0; mi < 2; mi++) {
                    int trow = t0 + wm * 32 + mi * 16 + er;
#pragma unroll
                    for (int ni = 0; ni < 8; ni++) {
                        int col = wn * 64 + ni * 8 + ec;
                        if (trow < Tsz) {
                            float2 v0 = make_float2(acc[mi][ni][0] + bias0[ni],
                                                    acc[mi][ni][1] + bias1[ni]);
                            *(float2*)&g_gx[((size_t)b * Tsz + trow) * Gsz + col] = v0;
                        }
                        if (trow + 8 < Tsz) {
                            float2 v1 = make_float2(acc[mi][ni][2] + bias0[ni],
                                                    acc[mi][ni][3] + bias1[ni]);
                            *(float2*)&g_gx[((size_t)b * Tsz + trow + 8) * Gsz + col] = v1;
                        }
                    }
                }
            }
            __threadfence_block();
            BARSYNC(1, 256);             // chunk ch published (phase-locked)
        }
    }
}

// ============================================================================
// Kernel 3: attention GEMM + fused qk/fc epilogue (unchanged)
// ============================================================================
#define BPAD 136
#define NIT2 (Tsz / 16)      // 50
__global__ __launch_bounds__(256, 2) void gemm_q_mma(
    const float* __restrict__ bw, const float* __restrict__ Wfc,
    float* __restrict__ qk_out) {
    __shared__ __align__(16) __nv_bfloat16 sAhi[2][128 * APAD], sAlo[2][128 * APAD];
    __shared__ __align__(16) __nv_bfloat16 sBhi[2][16 * BPAD],  sBlo[2][16 * BPAD];
    __shared__ float redfc[512];

    const int m0   = blockIdx.x * 128;
    const int n0   = blockIdx.y * 128;
    const int tid  = threadIdx.x;
    const int lane = tid & 31;
    const int wid  = tid >> 5;
    const int wm   = wid >> 1;
    const int wn   = wid & 1;

    float acc[2][8][4];
#pragma unroll
    for (int mi = 0; mi < 2; mi++)
#pragma unroll
        for (int ni = 0; ni < 8; ni++)
#pragma unroll
            for (int e = 0; e < 4; e++) acc[mi][ni][e] = 0.f;

    const int alr = tid >> 1;
    const int alk = (tid & 1) * 8;
    const int blr = tid >> 4;
    const int bln = (tid & 15) * 8;
    const bool arow_ok = (m0 + alr < Tsz);

    const int amrow = lane & 15;
    const int akcol = (lane >> 4) * 8;
    int offA[2];
#pragma unroll
    for (int mi = 0; mi < 2; mi++)
        offA[mi] = (wm * 32 + mi * 16 + amrow) * APAD + akcol;
    const int qbrow = lane & 15;
    const int qbcol = (lane >> 4) * 8;
    int offB[4];
#pragma unroll
    for (int nb = 0; nb < 4; nb++)
        offB[nb] = qbrow * BPAD + wn * 64 + nb * 16 + qbcol;

    uint4 pah, pal, pbh, pbl;
    auto loadA = [&](int k0) {
        if (arow_ok) {
            pah = *(const uint4*)&g_Ww_hi[(size_t)(m0 + alr) * Tsz + k0 + alk];
            pal = *(const uint4*)&g_Ww_lo[(size_t)(m0 + alr) * Tsz + k0 + alk];
        } else {
            pah = make_uint4(0, 0, 0, 0);
            pal = make_uint4(0, 0, 0, 0);
        }
    };
    auto loadB = [&](int k0) {
        pbh = *(const uint4*)&g_hsT_hi[(size_t)(k0 + blr) * NBH + n0 + bln];
        pbl = *(const uint4*)&g_hsT_lo[(size_t)(k0 + blr) * NBH + n0 + bln];
    };
    auto stA = [&](int buf) {
        *(uint4*)&sAhi[buf][alr * APAD + alk] = pah;
        *(uint4*)&sAlo[buf][alr * APAD + alk] = pal;
    };
    auto stB = [&](int buf) {
        *(uint4*)&sBhi[buf][blr * BPAD + bln] = pbh;
        *(uint4*)&sBlo[buf][blr * BPAD + bln] = pbl;
    };

    loadA(0); loadB(0);
    stA(0); stB(0);
    __syncthreads();

#pragma unroll 1
    for (int it = 0; it < NIT2; it++) {
        const int cur = it & 1;
        const bool more = (it + 1 < NIT2);
        if (more) { loadA((it + 1) * 16); loadB((it + 1) * 16); }

        uint32_t afr[2][4], alo2[2][4], bfr[8][2];
        ldsm4(afr[0], sptr(&sAhi[cur][offA[0]]));
        ldsm4(afr[1], sptr(&sAhi[cur][offA[1]]));
#pragma unroll
        for (int nb = 0; nb < 4; nb++) {
            uint32_t r[4];
            ldsm4t(r, sptr(&sBhi[cur][offB[nb]]));
            bfr[2 * nb][0] = r[0]; bfr[2 * nb][1] = r[1];
            bfr[2 * nb + 1][0] = r[2]; bfr[2 * nb + 1][1] = r[3];
        }
#pragma unroll
        for (int mi = 0; mi < 2; mi++)
#pragma unroll
            for (int ni = 0; ni < 8; ni++) mma16816(acc[mi][ni], afr[mi], bfr[ni]);

        ldsm4(alo2[0], sptr(&sAlo[cur][offA[0]]));
        ldsm4(alo2[1], sptr(&sAlo[cur][offA[1]]));
#pragma unroll
        for (int mi = 0; mi < 2; mi++)
#pragma unroll
            for (int ni = 0; ni < 8; ni++) mma16816(acc[mi][ni], alo2[mi], bfr[ni]);

#pragma unroll
        for (int nb = 0; nb < 4; nb++) {
            uint32_t r[4];
            ldsm4t(r, sptr(&sBlo[cur][offB[nb]]));
            bfr[2 * nb][0] = r[0]; bfr[2 * nb][1] = r[1];
            bfr[2 * nb + 1][0] = r[2]; bfr[2 * nb + 1][1] = r[3];
        }
#pragma unroll
        for (int mi = 0; mi < 2; mi++)
#pragma unroll
            for (int ni = 0; ni < 8; ni++) mma16816(acc[mi][ni], afr[mi], bfr[ni]);

        if (more) { stA(cur ^ 1); stB(cur ^ 1); }
        __syncthreads();
    }

    // ---- fused epilogue: qk = hsT*(q+bw), fc partials ----
    const int er = lane >> 2;
    const int ec = (lane & 3) * 2;
    float pb[2] = {0.f, 0.f};
#pragma unroll
    for (int mi = 0; mi < 2; mi++) {
        int r0 = m0 + wm * 32 + mi * 16 + er;
        int r1 = r0 + 8;
        float bw0 = (r0 < Tsz) ? bw[r0] : 0.f;
        float bw1 = (r1 < Tsz) ? bw[r1] : 0.f;
#pragma unroll
        for (int ni = 0; ni < 8; ni++) {
            int n  = n0 + wn * 64 + ni * 8 + ec;
            int bb = n >> 5, hh = n & 31;
            int bi = ni >> 2;
            if (r0 < Tsz) {
                float2 o = *(const float2*)&g_hsT[(size_t)r0 * NBH + n];
                float2 wf = *(const float2*)&Wfc[r0 * Hsz + hh];
                float2 v = make_float2(o.x * (acc[mi][ni][0] + bw0),
                                       o.y * (acc[mi][ni][1] + bw0));
                *(float2*)&qk_out[(size_t)bb * (Tsz * Hsz) + r0 * Hsz + hh] = v;
                pb[bi] = fmaf(v.x, wf.x, fmaf(v.y, wf.y, pb[bi]));
            }
            if (r1 < Tsz) {
                float2 o = *(const float2*)&g_hsT[(size_t)r1 * NBH + n];
                float2 wf = *(const float2*)&Wfc[r1 * Hsz + hh];
                float2 v = make_float2(o.x * (acc[mi][ni][2] + bw1),
                                       o.y * (acc[mi][ni][3] + bw1));
                *(float2*)&qk_out[(size_t)bb * (Tsz * Hsz) + r1 * Hsz + hh] = v;
                pb[bi] = fmaf(v.x, wf.x, fmaf(v.y, wf.y, pb[bi]));
            }
        }
    }
    redfc[(wn * 2 + 0) * 128 + wm * 32 + lane] = pb[0];
    redfc[(wn * 2 + 1) * 128 + wm * 32 + lane] = pb[1];
    __syncthreads();
    if (wid < 4) {
        float s = redfc[wid * 128 + lane] + redfc[wid * 128 + lane + 32]
                + redfc[wid * 128 + lane + 64] + redfc[wid * 128 + lane + 96];
#pragma unroll
        for (int o = 16; o > 0; o >>= 1) s += __shfl_xor_sync(0xffffffffu, s, o);
        if (lane == 0) g_fcpart[((n0 >> 5) + wid) * NMB + blockIdx.x] = s;
    }
}

// Final fc: out[b] = bfc + sum over 7 m-block partials
__global__ void fc_final(const float* __restrict__ bfc, float* __restrict__ fc_out) {
    int b = threadIdx.x;
    float s = bfc[0];
#pragma unroll
    for (int i = 0; i < NMB; i++) s += g_fcpart[b * NMB + i];
    fc_out[b] = s;
}

// ============================================================================
// Launcher
// ============================================================================
extern "C" void kernel_launch(void* const* d_in, const int* in_sizes, int n_in,
                              void* d_out, int out_size) {
    const float* x   = (const float*)d_in[0];
    const float* Wih = (const float*)d_in[1];
    const float* Whh = (const float*)d_in[2];
    const float* bih = (const float*)d_in[3];
    const float* bhh = (const float*)d_in[4];
    const float* Ww  = (const float*)d_in[5];
    const float* bw  = (const float*)d_in[6];
    const float* Wfc = (const float*)d_in[7];
    const float* bfc = (const float*)d_in[8];
    float* out = (float*)d_out;

    const long QK = (long)Bsz * Tsz * Hsz;
    float* fc_out;
    float* qk_out;
    if (out_size == (int)(QK + Bsz)) {
        fc_out = out;
        qk_out = out + Bsz;
    } else if (out_size == (int)QK) {
        qk_out = out;
        cudaGetSymbolAddress((void**)&fc_out, g_fc_scratch);
    } else {
        fc_out = out;
        cudaGetSymbolAddress((void**)&qk_out, g_qk_scratch);
    }

    // 0. one-time operand splits
    cvt_wih<<<(128 * IszP + 255) / 256, 256>>>(Wih);
    cvt_ww<<<(800 * 800 + 255) / 256, 256>>>(Ww);

    // 1+2. FUSED input-projection GEMM + LSTM scan (producer/consumer CTA)
    gx_lstm_fused<<<Bsz, 256>>>(x, Whh, bih, bhh);

    // 3. attention GEMM + fused qk/fc epilogue
    dim3 g2(NMB, NBH / 128);                 // (7, 32)
    gemm_q_mma<<<g2, 256>>>(bw, Wfc, qk_out);

    // 4. final fc reduction
    fc_final<<<1, Bsz>>>(bfc, fc_out);
}